// round 13
// baseline (speedup 1.0000x reference)
#include <cuda_runtime.h>
#include <cuda_fp16.h>
#include <math.h>
#include <string.h>
#include <stdint.h>

#define S_   2048
#define D_   2048
#define H_   16
#define DH_  128
#define E_   8
#define FF_  768
#define SFF_ 4096
#define EPS_ 1e-6f

typedef __half h16;

// ---------------- fp32 scratch ----------------------------------------------
__device__ float g_q[S_*D_];                   // h16 qkvg temps
__device__ float g_k[S_*D_];
__device__ float g_v[S_*D_];
__device__ float g_gl[S_*D_];
__device__ float g_ctx[S_*D_];                 // raw fp32 y scratch
__device__ float g_hbuf[S_*D_];
__device__ float g_sgf[S_*SFF_];               // h16 shared-gate out
__device__ float g_mactf[(size_t)S_*2*FF_];    // h16 moe-gate out
__device__ float g_shout[S_*D_];
__device__ float g_eo[(size_t)S_*2*D_];
__device__ float g_gsig[S_];
__device__ int   g_eidx[S_*2];
__device__ float g_ew[S_*2];
__device__ int   g_cnt[E_];
__device__ int   g_off[E_+1];
__device__ int   g_fill[E_];
__device__ int   g_perm[S_*2];
__device__ int   g_slot[S_*2];

// ---------------- fp16 scratch ----------------------------------------------
__device__ h16 b_x[S_*D_];
__device__ h16 b_q[S_*D_];
__device__ h16 b_k[S_*D_];
__device__ h16 b_vT[S_*D_];                    // [H][DH][S]
__device__ h16 b_up[S_*SFF_];                  // h16 "up" scratch (shared/moe)
__device__ h16 b_ctx[S_*D_];
__device__ h16 b_y[S_*D_];
__device__ h16 b_sg[S_*SFF_];
__device__ h16 b_mact[(size_t)S_*2*FF_];
// transposed fp16 weights (K-major: [N][K])
__device__ h16 b_wq[D_*D_];
__device__ h16 b_wk[D_*D_];
__device__ h16 b_wv[D_*D_];
__device__ h16 b_wg[D_*D_];
__device__ h16 b_wo[D_*D_];
__device__ h16 b_shg[(size_t)SFF_*D_];
__device__ h16 b_shu[(size_t)SFF_*D_];
__device__ h16 b_shd[(size_t)D_*SFF_];
__device__ h16 b_eg[(size_t)E_*FF_*D_];
__device__ h16 b_eu[(size_t)E_*FF_*D_];
__device__ h16 b_ed[(size_t)E_*D_*FF_];

// ================= PTX helpers ===============================================
__device__ __forceinline__ void cpasync16(uint32_t dst, const void* src) {
    asm volatile("cp.async.cg.shared.global [%0], [%1], 16;"
        :: "r"(dst), "l"((unsigned long long)__cvta_generic_to_global(src)));
}
__device__ __forceinline__ uint32_t smem_u32(const void* p) {
    uint32_t a;
    asm("{ .reg .u64 t; cvta.to.shared.u64 t, %1; cvt.u32.u64 %0, t; }" : "=r"(a) : "l"(p));
    return a;
}
__device__ __forceinline__ uint32_t h2u(__half2 h) {
    uint32_t u;
    memcpy(&u, &h, 4);
    return u;
}
__device__ __forceinline__ void mma16(float c[4], const uint32_t a[4], const uint32_t b[2]) {
    asm volatile("mma.sync.aligned.m16n8k16.row.col.f32.f16.f16.f32 "
        "{%0,%1,%2,%3}, {%4,%5,%6,%7}, {%8,%9}, {%0,%1,%2,%3};"
        : "+f"(c[0]), "+f"(c[1]), "+f"(c[2]), "+f"(c[3])
        : "r"(a[0]), "r"(a[1]), "r"(a[2]), "r"(a[3]), "r"(b[0]), "r"(b[1]));
}
__device__ __forceinline__ void ldsm_x4(uint32_t r[4], uint32_t addr) {
    asm volatile("ldmatrix.sync.aligned.m8n8.x4.shared.b16 {%0,%1,%2,%3}, [%4];"
        : "=r"(r[0]), "=r"(r[1]), "=r"(r[2]), "=r"(r[3]) : "r"(addr));
}

struct BC4 { const h16* B[4]; float* C[4]; };

// ================= fp16 mma.sync GEMM (round-10, unchanged) ==================
template<int MOE, int H16>
__global__ __launch_bounds__(256) void bgemm(
    const h16* __restrict__ A, long long lda, long long strideA,
    BC4 bc, long long ldb, long long strideB,
    long long ldc, long long strideC,
    const float* __restrict__ add_, long long ldadd, long long strideAdd,
    int M, int N, int K, float alpha, int splitN)
{
    int cnt = M, seg = 0;
    if (MOE) {
        int e = blockIdx.z;
        cnt = g_cnt[e]; seg = g_off[e];
        if ((int)(blockIdx.y * 128) >= cnt) return;
    }
    const int colTotal = blockIdx.x * 128;
    const int bi = colTotal / splitN;
    const int colBase = colTotal - bi * splitN;
    const h16* B = bc.B[bi];
    float* C = bc.C[bi];
    if (MOE) {
        B += (long long)blockIdx.z * strideB;
    } else {
        A += (long long)blockIdx.z * strideA;
        B += (long long)blockIdx.z * strideB;
        C += (long long)blockIdx.z * (H16 ? 0 : strideC);
        if (H16) C = (float*)((h16*)bc.C[bi] + (long long)blockIdx.z * strideC);
        if (add_) add_ += (long long)blockIdx.z * strideAdd;
    }
    const int rowBase = blockIdx.y * 128;

    extern __shared__ char smc[];
    const uint32_t s32 = smem_u32(smc);

    const int tid = threadIdx.x, lane = tid & 31, wid = tid >> 5;
    const int wm = wid & 3, wn = wid >> 2;

    const h16* aSrc[4]; uint32_t aOff[4];
    const h16* bSrc[4];
    #pragma unroll
    for (int i = 0; i < 4; i++) {
        int f = tid + i * 256;
        int row = f >> 3, ch = f & 7;
        int r = rowBase + row;
        long long arow;
        if (MOE == 1)      { int rr = min(r, cnt - 1); arow = g_perm[seg + rr]; }
        else if (MOE == 2) { int rr = min(r, cnt - 1); arow = seg + rr; }
        else               arow = r;
        aSrc[i] = A + arow * lda + ch * 8;
        aOff[i] = (uint32_t)(row * 144 + ch * 16);
        bSrc[i] = B + (long long)(colBase + row) * ldb + ch * 8;
    }

    uint32_t aLd[2], bLd[4];
    {
        int arow = wm * 32 + (lane & 7) + ((lane >> 3) & 1) * 8;
        uint32_t acol = ((lane >> 4) & 1) * 16;
        #pragma unroll
        for (int mt = 0; mt < 2; mt++)
            aLd[mt] = (uint32_t)((arow + mt * 16) * 144) + acol;
        int brow = wn * 64 + (lane & 7) + ((lane >> 4) & 1) * 8;
        uint32_t bcol = ((lane >> 3) & 1) * 16;
        #pragma unroll
        for (int p = 0; p < 4; p++)
            bLd[p] = (uint32_t)((brow + p * 16) * 144) + bcol;
    }

    float acc[2][8][4] = {};
    const int NC = K >> 6;

    #define ISSUE(c) do { \
        int _s = (c) % 3; \
        uint32_t _ab = s32 + (uint32_t)_s * 18432u; \
        uint32_t _bb = s32 + 55296u + (uint32_t)_s * 18432u; \
        _Pragma("unroll") \
        for (int _i = 0; _i < 4; _i++) { \
            cpasync16(_ab + aOff[_i], aSrc[_i] + (long long)(c) * 64); \
            cpasync16(_bb + aOff[_i], bSrc[_i] + (long long)(c) * 64); \
        } \
        asm volatile("cp.async.commit_group;"); \
    } while (0)

    ISSUE(0);
    if (NC > 1) ISSUE(1);
    for (int c = 0; c < NC; c++) {
        if (c + 1 < NC) asm volatile("cp.async.wait_group 1;");
        else            asm volatile("cp.async.wait_group 0;");
        __syncthreads();
        if (c + 2 < NC) ISSUE(c + 2);
        const uint32_t sAb = s32 + (uint32_t)(c % 3) * 18432u;
        const uint32_t sBb = s32 + 55296u + (uint32_t)(c % 3) * 18432u;
        #pragma unroll
        for (int kk = 0; kk < 4; kk++) {
            const uint32_t ko = (uint32_t)kk * 32u;
            uint32_t af[2][4];
            #pragma unroll
            for (int mt = 0; mt < 2; mt++)
                ldsm_x4(af[mt], sAb + aLd[mt] + ko);
            uint32_t bfr[8][2];
            #pragma unroll
            for (int p = 0; p < 4; p++) {
                uint32_t m[4];
                ldsm_x4(m, sBb + bLd[p] + ko);
                bfr[2*p][0]   = m[0]; bfr[2*p][1]   = m[1];
                bfr[2*p+1][0] = m[2]; bfr[2*p+1][1] = m[3];
            }
            #pragma unroll
            for (int mt = 0; mt < 2; mt++)
                #pragma unroll
                for (int nt = 0; nt < 8; nt++)
                    mma16(acc[mt][nt], af[mt], bfr[nt]);
        }
        __syncthreads();
    }
    #undef ISSUE

    #pragma unroll
    for (int mt = 0; mt < 2; mt++) {
        const int lr0 = rowBase + wm * 32 + mt * 16 + (lane >> 2);
        const int lr1 = lr0 + 8;
        const long long cr0 = MOE ? (long long)(seg + lr0) : (long long)lr0;
        const long long cr1 = MOE ? (long long)(seg + lr1) : (long long)lr1;
        const bool ok0 = MOE ? (lr0 < cnt) : true;
        const bool ok1 = MOE ? (lr1 < cnt) : true;
        #pragma unroll
        for (int nt = 0; nt < 8; nt++) {
            const int cc = colBase + wn * 64 + nt * 8 + (lane & 3) * 2;
            if (ok0) {
                float vx = alpha * acc[mt][nt][0], vy = alpha * acc[mt][nt][1];
                if (H16) {
                    __half2 h2 = __floats2half2_rn(vx, vy);
                    *(__half2*)&((h16*)C)[cr0 * ldc + cc] = h2;
                } else {
                    if (add_) {
                        float2 t = *(const float2*)&add_[(long long)lr0 * ldadd + cc];
                        vx += t.x; vy += t.y;
                    }
                    float2 v; v.x = vx; v.y = vy;
                    *(float2*)&C[cr0 * ldc + cc] = v;
                }
            }
            if (ok1) {
                float vx = alpha * acc[mt][nt][2], vy = alpha * acc[mt][nt][3];
                if (H16) {
                    __half2 h2 = __floats2half2_rn(vx, vy);
                    *(__half2*)&((h16*)C)[cr1 * ldc + cc] = h2;
                } else {
                    if (add_) {
                        float2 t = *(const float2*)&add_[(long long)lr1 * ldadd + cc];
                        vx += t.x; vy += t.y;
                    }
                    float2 v; v.x = vx; v.y = vy;
                    *(float2*)&C[cr1 * ldc + cc] = v;
                }
            }
        }
    }
}

// ================= flash attention (sigmoid-gate fused epilogue) ==============
// Grid (S/64, H), 128 threads (4 warps). Warp w: q rows [w*16, w*16+16).
// Online softmax in fp32 registers; P quantized to fp16 in-register for P@V.
// Epilogue: ctx_out = (O/l) * sigmoid(gl).
__global__ __launch_bounds__(128) void flash_k(
    const h16* __restrict__ Q, const h16* __restrict__ Kt,
    const h16* __restrict__ VT, const float* __restrict__ bias,
    const h16* __restrict__ gl, h16* __restrict__ ctx, float isd)
{
    const int h = blockIdx.y;
    const int qb = blockIdx.x;
    const int tid = threadIdx.x, lane = tid & 31, w = tid >> 5;

    extern __shared__ char smc[];
    const uint32_t s32 = smem_u32(smc);
    const uint32_t sQ = s32;
    const uint32_t sK = s32 + 17408u;
    const uint32_t sV = s32 + 52224u;

    const h16* Qg = Q + (size_t)(qb * 64) * D_ + h * DH_;
    const h16* Kg = Kt + h * DH_;
    const h16* Vg = VT + (size_t)h * DH_ * S_;

    #pragma unroll
    for (int i = 0; i < 8; i++) {
        int idx = tid + i * 128;
        int row = idx >> 4, ch = idx & 15;
        cpasync16(sQ + (uint32_t)(row * 272 + ch * 16), Qg + (size_t)row * D_ + ch * 8);
    }
    asm volatile("cp.async.commit_group;");

    #define ISSUE_KV(c) do { \
        uint32_t _kb = sK + (uint32_t)((c) & 1) * 17408u; \
        uint32_t _vb = sV + (uint32_t)((c) & 1) * 18432u; \
        _Pragma("unroll") \
        for (int _i = 0; _i < 8; _i++) { \
            int _idx = tid + _i * 128; \
            int _kr = _idx >> 4, _kc = _idx & 15; \
            cpasync16(_kb + (uint32_t)(_kr * 272 + _kc * 16), \
                      Kg + (size_t)((c) * 64 + _kr) * D_ + _kc * 8); \
            int _vr = _idx >> 3, _vc = _idx & 7; \
            cpasync16(_vb + (uint32_t)(_vr * 144 + _vc * 16), \
                      Vg + (size_t)_vr * S_ + (c) * 64 + _vc * 8); \
        } \
        asm volatile("cp.async.commit_group;"); \
    } while (0)

    ISSUE_KV(0);
    asm volatile("cp.async.wait_group 0;");
    __syncthreads();

    const uint32_t aBase = (uint32_t)((w * 16 + (lane & 7) + ((lane >> 3) & 1) * 8) * 272)
                         + ((lane >> 4) & 1) * 16;
    const uint32_t bRow  = (uint32_t)(((lane & 7) + ((lane >> 4) & 1) * 8));
    const uint32_t bColK = ((lane >> 3) & 1) * 16;

    uint32_t qf[8][4];
    #pragma unroll
    for (int kk = 0; kk < 8; kk++)
        ldsm_x4(qf[kk], sQ + aBase + kk * 32);

    float acc_o[16][4] = {};
    float mrow[2] = {-1e30f, -1e30f};
    float lrow[2] = {0.f, 0.f};

    const int qr0 = qb * 64 + w * 16 + (lane >> 2);
    const int NC = S_ / 64;

    for (int c = 0; c < NC; c++) {
        if (c + 1 < NC) { ISSUE_KV(c + 1); asm volatile("cp.async.wait_group 1;"); }
        else            { asm volatile("cp.async.wait_group 0;"); }
        __syncthreads();
        const uint32_t kb = sK + (uint32_t)(c & 1) * 17408u;
        const uint32_t vb = sV + (uint32_t)(c & 1) * 18432u;

        float sacc[8][4] = {};
        #pragma unroll
        for (int kk = 0; kk < 8; kk++) {
            uint32_t bfr[8][2];
            #pragma unroll
            for (int p = 0; p < 4; p++) {
                uint32_t m4[4];
                ldsm_x4(m4, kb + (bRow + p * 16) * 272 + bColK + kk * 32);
                bfr[2*p][0] = m4[0]; bfr[2*p][1] = m4[1];
                bfr[2*p+1][0] = m4[2]; bfr[2*p+1][1] = m4[3];
            }
            #pragma unroll
            for (int nt = 0; nt < 8; nt++)
                mma16(sacc[nt], qf[kk], bfr[nt]);
        }

        float mb0 = -1e30f, mb1 = -1e30f;
        #pragma unroll
        for (int nt = 0; nt < 8; nt++) {
            const int kc = c * 64 + nt * 8 + (lane & 3) * 2;
            float2 bb0 = *(const float2*)&bias[(size_t)qr0 * S_ + kc];
            float2 bb1 = *(const float2*)&bias[(size_t)(qr0 + 8) * S_ + kc];
            sacc[nt][0] = sacc[nt][0] * isd + bb0.x;
            sacc[nt][1] = sacc[nt][1] * isd + bb0.y;
            sacc[nt][2] = sacc[nt][2] * isd + bb1.x;
            sacc[nt][3] = sacc[nt][3] * isd + bb1.y;
            mb0 = fmaxf(mb0, fmaxf(sacc[nt][0], sacc[nt][1]));
            mb1 = fmaxf(mb1, fmaxf(sacc[nt][2], sacc[nt][3]));
        }
        #pragma unroll
        for (int d = 1; d <= 2; d <<= 1) {
            mb0 = fmaxf(mb0, __shfl_xor_sync(0xffffffffu, mb0, d));
            mb1 = fmaxf(mb1, __shfl_xor_sync(0xffffffffu, mb1, d));
        }
        const float mn0 = fmaxf(mrow[0], mb0), mn1 = fmaxf(mrow[1], mb1);
        const float f0 = __expf(mrow[0] - mn0), f1 = __expf(mrow[1] - mn1);
        mrow[0] = mn0; mrow[1] = mn1;
        lrow[0] *= f0; lrow[1] *= f1;
        #pragma unroll
        for (int nt = 0; nt < 16; nt++) {
            acc_o[nt][0] *= f0; acc_o[nt][1] *= f0;
            acc_o[nt][2] *= f1; acc_o[nt][3] *= f1;
        }

        uint32_t ph[8][2];
        float ls0 = 0.f, ls1 = 0.f;
        #pragma unroll
        for (int nt = 0; nt < 8; nt++) {
            float p0 = __expf(sacc[nt][0] - mn0);
            float p1 = __expf(sacc[nt][1] - mn0);
            float p2 = __expf(sacc[nt][2] - mn1);
            float p3 = __expf(sacc[nt][3] - mn1);
            ls0 += p0 + p1; ls1 += p2 + p3;
            ph[nt][0] = h2u(__floats2half2_rn(p0, p1));
            ph[nt][1] = h2u(__floats2half2_rn(p2, p3));
        }
        #pragma unroll
        for (int d = 1; d <= 2; d <<= 1) {
            ls0 += __shfl_xor_sync(0xffffffffu, ls0, d);
            ls1 += __shfl_xor_sync(0xffffffffu, ls1, d);
        }
        lrow[0] += ls0; lrow[1] += ls1;

        #pragma unroll
        for (int kk = 0; kk < 4; kk++) {
            uint32_t af[4];
            af[0] = ph[2*kk][0]; af[1] = ph[2*kk][1];
            af[2] = ph[2*kk+1][0]; af[3] = ph[2*kk+1][1];
            #pragma unroll
            for (int p = 0; p < 8; p++) {
                uint32_t m4[4];
                ldsm_x4(m4, vb + (bRow + p * 16) * 144 + bColK + kk * 32);
                uint32_t bf0[2] = {m4[0], m4[1]};
                uint32_t bf1[2] = {m4[2], m4[3]};
                mma16(acc_o[2*p], af, bf0);
                mma16(acc_o[2*p+1], af, bf1);
            }
        }
        __syncthreads();
    }
    #undef ISSUE_KV

    // epilogue: ctx = (O / l) * sigmoid(gl)
    const float inv0 = 1.f / lrow[0], inv1 = 1.f / lrow[1];
    const size_t base0 = (size_t)qr0 * D_ + h * DH_;
    const size_t base1 = base0 + (size_t)8 * D_;
    h16* crow0 = ctx + base0;
    h16* crow1 = ctx + base1;
    const h16* grow0 = gl + base0;
    const h16* grow1 = gl + base1;
    #pragma unroll
    for (int nt = 0; nt < 16; nt++) {
        const int cc = nt * 8 + (lane & 3) * 2;
        __half2 g0 = *(const __half2*)&grow0[cc];
        __half2 g1 = *(const __half2*)&grow1[cc];
        float s00 = 1.f / (1.f + __expf(-__half2float(__low2half(g0))));
        float s01 = 1.f / (1.f + __expf(-__half2float(__high2half(g0))));
        float s10 = 1.f / (1.f + __expf(-__half2float(__low2half(g1))));
        float s11 = 1.f / (1.f + __expf(-__half2float(__high2half(g1))));
        *(__half2*)&crow0[cc] = __floats2half2_rn(acc_o[nt][0] * inv0 * s00,
                                                  acc_o[nt][1] * inv0 * s01);
        *(__half2*)&crow1[cc] = __floats2half2_rn(acc_o[nt][2] * inv1 * s10,
                                                  acc_o[nt][3] * inv1 * s11);
    }
}

// ---------- fast transpose-convert: [R][C] fp32 -> [C][R] fp16, 128x64 -------
// 256 threads; 8 float4 loads in flight per thread (latency hiding).
__global__ __launch_bounds__(256) void tcvt128(
    const float* __restrict__ in, h16* __restrict__ out,
    int ldin, long long zin, int ldout, long long zout)
{
    __shared__ float sm[128][66];
    in  += (long long)blockIdx.z * zin;
    out += (long long)blockIdx.z * zout;
    int c0 = blockIdx.x * 64, r0 = blockIdx.y * 128;
    int tid = threadIdx.x;
    int lr = tid >> 4, lc4 = (tid & 15) * 4;
    #pragma unroll
    for (int i = 0; i < 8; i++) {
        float4 v = *(const float4*)&in[(long long)(r0 + lr + i*16) * ldin + c0 + lc4];
        sm[lr + i*16][lc4 + 0] = v.x; sm[lr + i*16][lc4 + 1] = v.y;
        sm[lr + i*16][lc4 + 2] = v.z; sm[lr + i*16][lc4 + 3] = v.w;
    }
    __syncthreads();
    #pragma unroll
    for (int i = 0; i < 8; i++) {
        int j = tid + i * 256;
        int c = j >> 5, r4 = (j & 31) * 4;
        uint2 w;
        h16* wb = (h16*)&w;
        wb[0] = __float2half_rn(sm[r4 + 0][c]);
        wb[1] = __float2half_rn(sm[r4 + 1][c]);
        wb[2] = __float2half_rn(sm[r4 + 2][c]);
        wb[3] = __float2half_rn(sm[r4 + 3][c]);
        *(uint2*)&out[(long long)(c0 + c) * ldout + r0 + r4] = w;
    }
}

// ---------- h16 -> h16 transpose, 64x64 ---------------------------------------
__global__ __launch_bounds__(256) void tcvt16(
    const h16* __restrict__ in, h16* __restrict__ out,
    int ldin, long long zin, int ldout, long long zout)
{
    __shared__ h16 sm[64][68];
    in  += (long long)blockIdx.z * zin;
    out += (long long)blockIdx.z * zout;
    int c0 = blockIdx.x * 64, r0 = blockIdx.y * 64;
    int tid = threadIdx.x;
    int lr = tid >> 4, lc4 = (tid & 15) * 4;
    #pragma unroll
    for (int i = 0; i < 4; i++) {
        uint2 v = *(const uint2*)&in[(long long)(r0 + lr + i*16) * ldin + c0 + lc4];
        *(uint2*)&sm[lr + i*16][lc4] = v;
    }
    __syncthreads();
    int oc = tid >> 4, or4 = (tid & 15) * 4;
    #pragma unroll
    for (int i = 0; i < 4; i++) {
        int c = oc + i * 16;
        uint2 w;
        h16* wb = (h16*)&w;
        wb[0] = sm[or4 + 0][c]; wb[1] = sm[or4 + 1][c];
        wb[2] = sm[or4 + 2][c]; wb[3] = sm[or4 + 3][c];
        *(uint2*)&out[(long long)(c0 + c) * ldout + r0 + or4] = w;
    }
}

// ---------------- elementwise / reduction kernels ---------------------------
__global__ void reset_k() { int i = threadIdx.x; if (i < E_) g_cnt[i] = 0; }

__global__ void rmsnorm_k(const float* __restrict__ in, const float* __restrict__ w,
                          h16* __restrict__ outB, float* __restrict__ outRaw)
{
    int s = blockIdx.x;
    const float* x = in + (size_t)s * D_;
    float ss = 0.f;
    for (int d = threadIdx.x; d < D_; d += 256) { float v = x[d]; ss += v*v; }
    __shared__ float red[256];
    red[threadIdx.x] = ss; __syncthreads();
    for (int st = 128; st > 0; st >>= 1) {
        if (threadIdx.x < st) red[threadIdx.x] += red[threadIdx.x+st];
        __syncthreads();
    }
    float r = rsqrtf(red[0]/(float)D_ + EPS_);
    for (int d = threadIdx.x; d < D_; d += 256) {
        float v = x[d]*r*(1.f + w[d]);
        outB[(size_t)s*D_ + d] = __float2half_rn(v);
        if (outRaw) outRaw[(size_t)s*D_ + d] = v;
    }
}

__global__ void rope16_k(const h16* __restrict__ q, const h16* __restrict__ k,
                         h16* __restrict__ qo, h16* __restrict__ ko,
                         const float* __restrict__ cosp, const float* __restrict__ sinp)
{
    int idx = blockIdx.x*blockDim.x + threadIdx.x;
    if (idx >= S_*H_*64) return;
    int d = idx & 63;
    int h = (idx >> 6) & 15;
    int s = idx >> 10;
    float c1 = cosp[s*DH_ + d],      s1 = sinp[s*DH_ + d];
    float c2 = cosp[s*DH_ + d + 64], s2 = sinp[s*DH_ + d + 64];
    size_t base = (size_t)s*D_ + h*DH_ + d;
    float q1 = __half2float(q[base]), q2 = __half2float(q[base+64]);
    qo[base]    = __float2half_rn(q1*c1 - q2*s1);
    qo[base+64] = __float2half_rn(q2*c2 + q1*s2);
    float k1 = __half2float(k[base]), k2 = __half2float(k[base+64]);
    ko[base]    = __float2half_rn(k1*c1 - k2*s1);
    ko[base+64] = __float2half_rn(k2*c2 + k1*s2);
}

__global__ void silumul16_k(const h16* __restrict__ a, const h16* __restrict__ b,
                            h16* __restrict__ outp, int n)
{
    int i = blockIdx.x*blockDim.x + threadIdx.x;
    if (i >= n) return;
    float g = __half2float(a[i]);
    outp[i] = __float2half_rn(g / (1.f + expf(-g)) * __half2float(b[i]));
}

__global__ void router_k(const float* __restrict__ Y, const float* __restrict__ Rw)
{
    int t = blockIdx.x;
    int tid = threadIdx.x;
    float part[E_] = {};
    for (int d = tid; d < D_; d += 256) {
        float v = Y[(size_t)t*D_ + d];
        #pragma unroll
        for (int e = 0; e < E_; e++) part[e] += v * Rw[d*E_ + e];
    }
    __shared__ float red[256];
    __shared__ float logits[E_];
    for (int e = 0; e < E_; e++) {
        red[tid] = part[e]; __syncthreads();
        for (int st = 128; st > 0; st >>= 1) {
            if (tid < st) red[tid] += red[tid+st];
            __syncthreads();
        }
        if (tid == 0) logits[e] = red[0];
        __syncthreads();
    }
    if (tid == 0) {
        float m = -1e30f;
        for (int e = 0; e < E_; e++) m = fmaxf(m, logits[e]);
        float p[E_], s = 0.f;
        for (int e = 0; e < E_; e++) { p[e] = expf(logits[e]-m); s += p[e]; }
        for (int e = 0; e < E_; e++) p[e] /= s;
        int i0 = 0;
        for (int e = 1; e < E_; e++) if (p[e] > p[i0]) i0 = e;
        int i1 = (i0 == 0) ? 1 : 0;
        for (int e = 0; e < E_; e++) if (e != i0 && p[e] > p[i1]) i1 = e;
        float sum = p[i0] + p[i1];
        g_eidx[t*2]   = i0; g_eidx[t*2+1] = i1;
        g_ew[t*2]     = p[i0]/sum;
        g_ew[t*2+1]   = p[i1]/sum;
        atomicAdd(&g_cnt[i0], 1);
        atomicAdd(&g_cnt[i1], 1);
    }
}

__global__ void offsets_k()
{
    if (threadIdx.x == 0 && blockIdx.x == 0) {
        int acc = 0;
        for (int e = 0; e < E_; e++) { g_off[e] = acc; g_fill[e] = acc; acc += g_cnt[e]; }
        g_off[E_] = acc;
    }
}

__global__ void scatter_k()
{
    int t = blockIdx.x*blockDim.x + threadIdx.x;
    if (t >= S_) return;
    #pragma unroll
    for (int k = 0; k < 2; k++) {
        int e = g_eidx[t*2+k];
        int pos = atomicAdd(&g_fill[e], 1);
        g_perm[pos] = t;
        g_slot[t*2+k] = pos;
    }
}

__global__ void gsig_k(const float* __restrict__ Y, const float* __restrict__ gw)
{
    int t = blockIdx.x;
    float s = 0.f;
    for (int d = threadIdx.x; d < D_; d += 256) s += Y[(size_t)t*D_ + d] * gw[d];
    __shared__ float red[256];
    red[threadIdx.x] = s; __syncthreads();
    for (int st = 128; st > 0; st >>= 1) {
        if (threadIdx.x < st) red[threadIdx.x] += red[threadIdx.x+st];
        __syncthreads();
    }
    if (threadIdx.x == 0) g_gsig[t] = 1.f / (1.f + expf(-red[0]));
}

__global__ void final_k(float* __restrict__ out)
{
    int i = blockIdx.x*blockDim.x + threadIdx.x;
    if (i >= S_*D_) return;
    int t = i >> 11;
    int d = i & 2047;
    float m0 = g_ew[2*t]   * g_eo[(size_t)g_slot[2*t]  *D_ + d];
    float m1 = g_ew[2*t+1] * g_eo[(size_t)g_slot[2*t+1]*D_ + d];
    out[i] = g_hbuf[i] + m0 + m1 + g_shout[i]*g_gsig[t];
}

// ---------------- host launcher ---------------------------------------------
extern "C" void kernel_launch(void* const* d_in, const int* in_sizes, int n_in,
                              void* d_out, int out_size)
{
    const float* hidden = (const float*)d_in[0];
    const float* bias   = (const float*)d_in[1];
    const float* cosp   = (const float*)d_in[2];
    const float* sinp   = (const float*)d_in[3];
    const float* ln1w   = (const float*)d_in[4];
    const float* ln2w   = (const float*)d_in[5];
    const float* wq     = (const float*)d_in[6];
    const float* wk     = (const float*)d_in[7];
    const float* wv     = (const float*)d_in[8];
    const float* wg     = (const float*)d_in[9];
    const float* wo     = (const float*)d_in[10];
    const float* rw     = (const float*)d_in[11];
    const float* eg     = (const float*)d_in[12];
    const float* eu     = (const float*)d_in[13];
    const float* ed     = (const float*)d_in[14];
    const float* shg    = (const float*)d_in[15];
    const float* shu    = (const float*)d_in[16];
    const float* shd    = (const float*)d_in[17];
    const float* shgw   = (const float*)d_in[18];
    float* out = (float*)d_out;

    float *pq, *pk, *pv, *pgl, *pctx, *ph, *psgf, *pmactf, *pshout, *peo;
    cudaGetSymbolAddress((void**)&pq,    g_q);
    cudaGetSymbolAddress((void**)&pk,    g_k);
    cudaGetSymbolAddress((void**)&pv,    g_v);
    cudaGetSymbolAddress((void**)&pgl,   g_gl);
    cudaGetSymbolAddress((void**)&pctx,  g_ctx);
    cudaGetSymbolAddress((void**)&ph,    g_hbuf);
    cudaGetSymbolAddress((void**)&psgf,  g_sgf);
    cudaGetSymbolAddress((void**)&pmactf,g_mactf);
    cudaGetSymbolAddress((void**)&pshout,g_shout);
    cudaGetSymbolAddress((void**)&peo,   g_eo);

    h16 *bx, *bq, *bk, *bvT, *bup, *bctx, *by, *bsg, *bmact;
    h16 *Bwq, *Bwk, *Bwv, *Bwg, *Bwo, *Bshg, *Bshu, *Bshd, *Beg, *Beu, *Bed;
    cudaGetSymbolAddress((void**)&bx,   b_x);
    cudaGetSymbolAddress((void**)&bq,   b_q);
    cudaGetSymbolAddress((void**)&bk,   b_k);
    cudaGetSymbolAddress((void**)&bvT,  b_vT);
    cudaGetSymbolAddress((void**)&bup,  b_up);
    cudaGetSymbolAddress((void**)&bctx, b_ctx);
    cudaGetSymbolAddress((void**)&by,   b_y);
    cudaGetSymbolAddress((void**)&bsg,  b_sg);
    cudaGetSymbolAddress((void**)&bmact,b_mact);
    cudaGetSymbolAddress((void**)&Bwq,  b_wq);
    cudaGetSymbolAddress((void**)&Bwk,  b_wk);
    cudaGetSymbolAddress((void**)&Bwv,  b_wv);
    cudaGetSymbolAddress((void**)&Bwg,  b_wg);
    cudaGetSymbolAddress((void**)&Bwo,  b_wo);
    cudaGetSymbolAddress((void**)&Bshg, b_shg);
    cudaGetSymbolAddress((void**)&Bshu, b_shu);
    cudaGetSymbolAddress((void**)&Bshd, b_shd);
    cudaGetSymbolAddress((void**)&Beg,  b_eg);
    cudaGetSymbolAddress((void**)&Beu,  b_eu);
    cudaGetSymbolAddress((void**)&Bed,  b_ed);

    h16* pq16   = (h16*)pq;
    h16* pk16   = (h16*)pk;
    h16* pv16   = (h16*)pv;
    h16* pgl16  = (h16*)pgl;
    h16* psg16  = (h16*)psgf;
    h16* pmact16= (h16*)pmactf;
    float* pyraw = pctx;

    const int SMEM = 110592;
    cudaFuncSetAttribute(bgemm<0,0>, cudaFuncAttributeMaxDynamicSharedMemorySize, SMEM);
    cudaFuncSetAttribute(bgemm<0,1>, cudaFuncAttributeMaxDynamicSharedMemorySize, SMEM);
    cudaFuncSetAttribute(bgemm<1,1>, cudaFuncAttributeMaxDynamicSharedMemorySize, SMEM);
    cudaFuncSetAttribute(bgemm<2,0>, cudaFuncAttributeMaxDynamicSharedMemorySize, SMEM);
    const int SMEM_F = 17408 + 2*17408 + 2*18432;   // 89088
    cudaFuncSetAttribute(flash_k, cudaFuncAttributeMaxDynamicSharedMemorySize, SMEM_F);

    const float isd = 0.08838834764831845f;

    reset_k<<<1, 32>>>();

    // ---- weight transpose-convert to fp16 K-major [N][K] ----
    tcvt128<<<dim3(32,16), 256>>>(wq, Bwq, D_, 0, D_, 0);
    tcvt128<<<dim3(32,16), 256>>>(wk, Bwk, D_, 0, D_, 0);
    tcvt128<<<dim3(32,16), 256>>>(wv, Bwv, D_, 0, D_, 0);
    tcvt128<<<dim3(32,16), 256>>>(wg, Bwg, D_, 0, D_, 0);
    tcvt128<<<dim3(32,16), 256>>>(wo, Bwo, D_, 0, D_, 0);
    tcvt128<<<dim3(64,16), 256>>>(shg, Bshg, SFF_, 0, D_, 0);
    tcvt128<<<dim3(64,16), 256>>>(shu, Bshu, SFF_, 0, D_, 0);
    tcvt128<<<dim3(32,32), 256>>>(shd, Bshd, D_, 0, SFF_, 0);
    tcvt128<<<dim3(12,16,E_), 256>>>(eg, Beg, FF_, (long long)D_*FF_, D_, (long long)FF_*D_);
    tcvt128<<<dim3(12,16,E_), 256>>>(eu, Beu, FF_, (long long)D_*FF_, D_, (long long)FF_*D_);
    tcvt128<<<dim3(32,6,E_), 256>>>(ed, Bed, D_, (long long)FF_*D_, FF_, (long long)D_*FF_);

    // ---- attention ----
    rmsnorm_k<<<S_, 256>>>(hidden, ln1w, bx, nullptr);
    {
        BC4 bc = {{Bwq, Bwk, Bwv, Bwg}, {(float*)pq16, (float*)pk16, (float*)pv16, (float*)pgl16}};
        bgemm<0,1><<<dim3(64,16), 256, SMEM>>>(bx, D_, 0, bc, D_, 0, D_, 0,
                                               nullptr, 0, 0, S_, 8192, D_, 1.f, 2048);
    }
    rope16_k<<<(S_*H_*64 + 255)/256, 256>>>(pq16, pk16, bq, bk, cosp, sinp);
    tcvt16<<<dim3(2,32,H_), 256>>>(pv16, bvT, D_, 128LL, S_, (long long)DH_*S_);

    // flash attention with fused sigmoid gate -> bctx
    flash_k<<<dim3(S_/64, H_), 128, SMEM_F>>>(bq, bk, bvT, bias, pgl16, bctx, isd);

    {
        BC4 bc = {{Bwo, 0, 0, 0}, {ph, 0, 0, 0}};
        bgemm<0,0><<<dim3(16,16), 256, SMEM>>>(bctx, D_, 0, bc, D_, 0, D_, 0,
                                               hidden, D_, 0, S_, D_, D_, 1.f, 2048);
    }

    // ---- routing (raw fp32 y) ----
    rmsnorm_k<<<S_, 256>>>(ph, ln2w, by, pyraw);
    router_k<<<S_, 256>>>(pyraw, rw);
    offsets_k<<<1, 1>>>();
    scatter_k<<<(S_ + 255)/256, 256>>>();
    gsig_k<<<S_, 256>>>(pyraw, shgw);

    // ---- shared expert ----
    {
        BC4 bc = {{Bshg, Bshu, 0, 0}, {(float*)psg16, (float*)bup, 0, 0}};
        bgemm<0,1><<<dim3(64,16), 256, SMEM>>>(by, D_, 0, bc, D_, 0, SFF_, 0,
                                               nullptr, 0, 0, S_, 8192, D_, 1.f, 4096);
    }
    silumul16_k<<<(S_*SFF_ + 255)/256, 256>>>(psg16, bup, bsg, S_*SFF_);
    {
        BC4 bc = {{Bshd, 0, 0, 0}, {pshout, 0, 0, 0}};
        bgemm<0,0><<<dim3(16,16), 256, SMEM>>>(bsg, SFF_, 0, bc, SFF_, 0, D_, 0,
                                               nullptr, 0, 0, S_, D_, SFF_, 1.f, 2048);
    }

    // ---- MoE experts (grouped) ----
    {
        BC4 bc = {{Beg, Beu, 0, 0}, {(float*)pmact16, (float*)bup, 0, 0}};
        bgemm<1,1><<<dim3(12,16,E_), 256, SMEM>>>(by, D_, 0, bc, D_, (long long)FF_*D_,
                                                  FF_, 0, nullptr, 0, 0,
                                                  0, 1536, D_, 1.f, 768);
    }
    silumul16_k<<<(S_*2*FF_ + 255)/256, 256>>>(pmact16, bup, bmact, S_*2*FF_);
    {
        BC4 bc = {{Bed, 0, 0, 0}, {peo, 0, 0, 0}};
        bgemm<2,0><<<dim3(16,16,E_), 256, SMEM>>>(bmact, FF_, 0, bc, FF_, (long long)D_*FF_,
                                                  D_, 0, nullptr, 0, 0,
                                                  0, D_, FF_, 1.f, 2048);
    }

    final_k<<<(S_*D_ + 255)/256, 256>>>(out);
}

// round 14
// speedup vs baseline: 1.0814x; 1.0814x over previous
#include <cuda_runtime.h>
#include <cuda_fp16.h>
#include <math.h>
#include <string.h>
#include <stdint.h>

#define S_   2048
#define D_   2048
#define H_   16
#define DH_  128
#define E_   8
#define FF_  768
#define SFF_ 4096
#define EPS_ 1e-6f

typedef __half h16;

// ---------------- fp32 scratch ----------------------------------------------
__device__ float g_q[S_*D_];                   // h16 qkvg temps
__device__ float g_k[S_*D_];
__device__ float g_v[S_*D_];
__device__ float g_gl[S_*D_];
__device__ float g_ctx[S_*D_];                 // h16 ctx, then raw fp32 y
__device__ float g_hbuf[S_*D_];
__device__ float g_sgf[S_*SFF_];               // h16 shared-gate out
__device__ float g_mactf[(size_t)S_*2*FF_];    // h16 moe-gate out
__device__ float g_shout[S_*D_];
__device__ float g_eo[(size_t)S_*2*D_];
__device__ float g_gsig[S_];
__device__ int   g_eidx[S_*2];
__device__ float g_ew[S_*2];
__device__ int   g_cnt[E_];
__device__ int   g_off[E_+1];
__device__ int   g_fill[E_];
__device__ int   g_perm[S_*2];
__device__ int   g_slot[S_*2];

// ---------------- fp16 scratch ----------------------------------------------
__device__ h16 b_x[S_*D_];
__device__ h16 b_q[S_*D_];
__device__ h16 b_k[S_*D_];
__device__ h16 b_vT[S_*D_];                    // [H][DH][S]
__device__ h16 b_up[S_*SFF_];                  // h16 "up" scratch (shared/moe)
__device__ h16 b_ctx[S_*D_];
__device__ h16 b_y[S_*D_];
__device__ h16 b_sg[S_*SFF_];
__device__ h16 b_mact[(size_t)S_*2*FF_];
// transposed fp16 weights (K-major: [N][K])
__device__ h16 b_wq[D_*D_];
__device__ h16 b_wk[D_*D_];
__device__ h16 b_wv[D_*D_];
__device__ h16 b_wg[D_*D_];
__device__ h16 b_wo[D_*D_];
__device__ h16 b_shg[(size_t)SFF_*D_];
__device__ h16 b_shu[(size_t)SFF_*D_];
__device__ h16 b_shd[(size_t)D_*SFF_];
__device__ h16 b_eg[(size_t)E_*FF_*D_];
__device__ h16 b_eu[(size_t)E_*FF_*D_];
__device__ h16 b_ed[(size_t)E_*D_*FF_];

// ================= PTX helpers ===============================================
__device__ __forceinline__ void cpasync16(uint32_t dst, const void* src) {
    asm volatile("cp.async.cg.shared.global [%0], [%1], 16;"
        :: "r"(dst), "l"((unsigned long long)__cvta_generic_to_global(src)));
}
__device__ __forceinline__ uint32_t smem_u32(const void* p) {
    uint32_t a;
    asm("{ .reg .u64 t; cvta.to.shared.u64 t, %1; cvt.u32.u64 %0, t; }" : "=r"(a) : "l"(p));
    return a;
}
__device__ __forceinline__ uint32_t h2u(__half2 h) {
    uint32_t u;
    memcpy(&u, &h, 4);
    return u;
}
__device__ __forceinline__ void mma16(float c[4], const uint32_t a[4], const uint32_t b[2]) {
    asm volatile("mma.sync.aligned.m16n8k16.row.col.f32.f16.f16.f32 "
        "{%0,%1,%2,%3}, {%4,%5,%6,%7}, {%8,%9}, {%0,%1,%2,%3};"
        : "+f"(c[0]), "+f"(c[1]), "+f"(c[2]), "+f"(c[3])
        : "r"(a[0]), "r"(a[1]), "r"(a[2]), "r"(a[3]), "r"(b[0]), "r"(b[1]));
}
__device__ __forceinline__ void ldsm_x4(uint32_t r[4], uint32_t addr) {
    asm volatile("ldmatrix.sync.aligned.m8n8.x4.shared.b16 {%0,%1,%2,%3}, [%4];"
        : "=r"(r[0]), "=r"(r[1]), "=r"(r[2]), "=r"(r[3]) : "r"(addr));
}

struct BC4 { const h16* B[4]; float* C[4]; };

// ================= fp16 mma.sync GEMM (round-10, unchanged) ==================
template<int MOE, int H16>
__global__ __launch_bounds__(256) void bgemm(
    const h16* __restrict__ A, long long lda, long long strideA,
    BC4 bc, long long ldb, long long strideB,
    long long ldc, long long strideC,
    const float* __restrict__ add_, long long ldadd, long long strideAdd,
    int M, int N, int K, float alpha, int splitN)
{
    int cnt = M, seg = 0;
    if (MOE) {
        int e = blockIdx.z;
        cnt = g_cnt[e]; seg = g_off[e];
        if ((int)(blockIdx.y * 128) >= cnt) return;
    }
    const int colTotal = blockIdx.x * 128;
    const int bi = colTotal / splitN;
    const int colBase = colTotal - bi * splitN;
    const h16* B = bc.B[bi];
    float* C = bc.C[bi];
    if (MOE) {
        B += (long long)blockIdx.z * strideB;
    } else {
        A += (long long)blockIdx.z * strideA;
        B += (long long)blockIdx.z * strideB;
        C += (long long)blockIdx.z * (H16 ? 0 : strideC);
        if (H16) C = (float*)((h16*)bc.C[bi] + (long long)blockIdx.z * strideC);
        if (add_) add_ += (long long)blockIdx.z * strideAdd;
    }
    const int rowBase = blockIdx.y * 128;

    extern __shared__ char smc[];
    const uint32_t s32 = smem_u32(smc);

    const int tid = threadIdx.x, lane = tid & 31, wid = tid >> 5;
    const int wm = wid & 3, wn = wid >> 2;

    const h16* aSrc[4]; uint32_t aOff[4];
    const h16* bSrc[4];
    #pragma unroll
    for (int i = 0; i < 4; i++) {
        int f = tid + i * 256;
        int row = f >> 3, ch = f & 7;
        int r = rowBase + row;
        long long arow;
        if (MOE == 1)      { int rr = min(r, cnt - 1); arow = g_perm[seg + rr]; }
        else if (MOE == 2) { int rr = min(r, cnt - 1); arow = seg + rr; }
        else               arow = r;
        aSrc[i] = A + arow * lda + ch * 8;
        aOff[i] = (uint32_t)(row * 144 + ch * 16);
        bSrc[i] = B + (long long)(colBase + row) * ldb + ch * 8;
    }

    uint32_t aLd[2], bLd[4];
    {
        int arow = wm * 32 + (lane & 7) + ((lane >> 3) & 1) * 8;
        uint32_t acol = ((lane >> 4) & 1) * 16;
        #pragma unroll
        for (int mt = 0; mt < 2; mt++)
            aLd[mt] = (uint32_t)((arow + mt * 16) * 144) + acol;
        int brow = wn * 64 + (lane & 7) + ((lane >> 4) & 1) * 8;
        uint32_t bcol = ((lane >> 3) & 1) * 16;
        #pragma unroll
        for (int p = 0; p < 4; p++)
            bLd[p] = (uint32_t)((brow + p * 16) * 144) + bcol;
    }

    float acc[2][8][4] = {};
    const int NC = K >> 6;

    #define ISSUE(c) do { \
        int _s = (c) % 3; \
        uint32_t _ab = s32 + (uint32_t)_s * 18432u; \
        uint32_t _bb = s32 + 55296u + (uint32_t)_s * 18432u; \
        _Pragma("unroll") \
        for (int _i = 0; _i < 4; _i++) { \
            cpasync16(_ab + aOff[_i], aSrc[_i] + (long long)(c) * 64); \
            cpasync16(_bb + aOff[_i], bSrc[_i] + (long long)(c) * 64); \
        } \
        asm volatile("cp.async.commit_group;"); \
    } while (0)

    ISSUE(0);
    if (NC > 1) ISSUE(1);
    for (int c = 0; c < NC; c++) {
        if (c + 1 < NC) asm volatile("cp.async.wait_group 1;");
        else            asm volatile("cp.async.wait_group 0;");
        __syncthreads();
        if (c + 2 < NC) ISSUE(c + 2);
        const uint32_t sAb = s32 + (uint32_t)(c % 3) * 18432u;
        const uint32_t sBb = s32 + 55296u + (uint32_t)(c % 3) * 18432u;
        #pragma unroll
        for (int kk = 0; kk < 4; kk++) {
            const uint32_t ko = (uint32_t)kk * 32u;
            uint32_t af[2][4];
            #pragma unroll
            for (int mt = 0; mt < 2; mt++)
                ldsm_x4(af[mt], sAb + aLd[mt] + ko);
            uint32_t bfr[8][2];
            #pragma unroll
            for (int p = 0; p < 4; p++) {
                uint32_t m[4];
                ldsm_x4(m, sBb + bLd[p] + ko);
                bfr[2*p][0]   = m[0]; bfr[2*p][1]   = m[1];
                bfr[2*p+1][0] = m[2]; bfr[2*p+1][1] = m[3];
            }
            #pragma unroll
            for (int mt = 0; mt < 2; mt++)
                #pragma unroll
                for (int nt = 0; nt < 8; nt++)
                    mma16(acc[mt][nt], af[mt], bfr[nt]);
        }
        __syncthreads();
    }
    #undef ISSUE

    #pragma unroll
    for (int mt = 0; mt < 2; mt++) {
        const int lr0 = rowBase + wm * 32 + mt * 16 + (lane >> 2);
        const int lr1 = lr0 + 8;
        const long long cr0 = MOE ? (long long)(seg + lr0) : (long long)lr0;
        const long long cr1 = MOE ? (long long)(seg + lr1) : (long long)lr1;
        const bool ok0 = MOE ? (lr0 < cnt) : true;
        const bool ok1 = MOE ? (lr1 < cnt) : true;
        #pragma unroll
        for (int nt = 0; nt < 8; nt++) {
            const int cc = colBase + wn * 64 + nt * 8 + (lane & 3) * 2;
            if (ok0) {
                float vx = alpha * acc[mt][nt][0], vy = alpha * acc[mt][nt][1];
                if (H16) {
                    __half2 h2 = __floats2half2_rn(vx, vy);
                    *(__half2*)&((h16*)C)[cr0 * ldc + cc] = h2;
                } else {
                    if (add_) {
                        float2 t = *(const float2*)&add_[(long long)lr0 * ldadd + cc];
                        vx += t.x; vy += t.y;
                    }
                    float2 v; v.x = vx; v.y = vy;
                    *(float2*)&C[cr0 * ldc + cc] = v;
                }
            }
            if (ok1) {
                float vx = alpha * acc[mt][nt][2], vy = alpha * acc[mt][nt][3];
                if (H16) {
                    __half2 h2 = __floats2half2_rn(vx, vy);
                    *(__half2*)&((h16*)C)[cr1 * ldc + cc] = h2;
                } else {
                    if (add_) {
                        float2 t = *(const float2*)&add_[(long long)lr1 * ldadd + cc];
                        vx += t.x; vy += t.y;
                    }
                    float2 v; v.x = vx; v.y = vy;
                    *(float2*)&C[cr1 * ldc + cc] = v;
                }
            }
        }
    }
}

// ================= flash attention (round-12 version) =========================
__global__ __launch_bounds__(128) void flash_k(
    const h16* __restrict__ Q, const h16* __restrict__ Kt,
    const h16* __restrict__ VT, const float* __restrict__ bias,
    h16* __restrict__ ctx, float isd)
{
    const int h = blockIdx.y;
    const int qb = blockIdx.x;
    const int tid = threadIdx.x, lane = tid & 31, w = tid >> 5;

    extern __shared__ char smc[];
    const uint32_t s32 = smem_u32(smc);
    const uint32_t sQ = s32;
    const uint32_t sK = s32 + 17408u;
    const uint32_t sV = s32 + 52224u;

    const h16* Qg = Q + (size_t)(qb * 64) * D_ + h * DH_;
    const h16* Kg = Kt + h * DH_;
    const h16* Vg = VT + (size_t)h * DH_ * S_;

    #pragma unroll
    for (int i = 0; i < 8; i++) {
        int idx = tid + i * 128;
        int row = idx >> 4, ch = idx & 15;
        cpasync16(sQ + (uint32_t)(row * 272 + ch * 16), Qg + (size_t)row * D_ + ch * 8);
    }
    asm volatile("cp.async.commit_group;");

    #define ISSUE_KV(c) do { \
        uint32_t _kb = sK + (uint32_t)((c) & 1) * 17408u; \
        uint32_t _vb = sV + (uint32_t)((c) & 1) * 18432u; \
        _Pragma("unroll") \
        for (int _i = 0; _i < 8; _i++) { \
            int _idx = tid + _i * 128; \
            int _kr = _idx >> 4, _kc = _idx & 15; \
            cpasync16(_kb + (uint32_t)(_kr * 272 + _kc * 16), \
                      Kg + (size_t)((c) * 64 + _kr) * D_ + _kc * 8); \
            int _vr = _idx >> 3, _vc = _idx & 7; \
            cpasync16(_vb + (uint32_t)(_vr * 144 + _vc * 16), \
                      Vg + (size_t)_vr * S_ + (c) * 64 + _vc * 8); \
        } \
        asm volatile("cp.async.commit_group;"); \
    } while (0)

    ISSUE_KV(0);
    asm volatile("cp.async.wait_group 0;");
    __syncthreads();

    const uint32_t aBase = (uint32_t)((w * 16 + (lane & 7) + ((lane >> 3) & 1) * 8) * 272)
                         + ((lane >> 4) & 1) * 16;
    const uint32_t bRow  = (uint32_t)(((lane & 7) + ((lane >> 4) & 1) * 8));
    const uint32_t bColK = ((lane >> 3) & 1) * 16;

    uint32_t qf[8][4];
    #pragma unroll
    for (int kk = 0; kk < 8; kk++)
        ldsm_x4(qf[kk], sQ + aBase + kk * 32);

    float acc_o[16][4] = {};
    float mrow[2] = {-1e30f, -1e30f};
    float lrow[2] = {0.f, 0.f};

    const int qr0 = qb * 64 + w * 16 + (lane >> 2);
    const int NC = S_ / 64;

    for (int c = 0; c < NC; c++) {
        if (c + 1 < NC) { ISSUE_KV(c + 1); asm volatile("cp.async.wait_group 1;"); }
        else            { asm volatile("cp.async.wait_group 0;"); }
        __syncthreads();
        const uint32_t kb = sK + (uint32_t)(c & 1) * 17408u;
        const uint32_t vb = sV + (uint32_t)(c & 1) * 18432u;

        float sacc[8][4] = {};
        #pragma unroll
        for (int kk = 0; kk < 8; kk++) {
            uint32_t bfr[8][2];
            #pragma unroll
            for (int p = 0; p < 4; p++) {
                uint32_t m4[4];
                ldsm_x4(m4, kb + (bRow + p * 16) * 272 + bColK + kk * 32);
                bfr[2*p][0] = m4[0]; bfr[2*p][1] = m4[1];
                bfr[2*p+1][0] = m4[2]; bfr[2*p+1][1] = m4[3];
            }
            #pragma unroll
            for (int nt = 0; nt < 8; nt++)
                mma16(sacc[nt], qf[kk], bfr[nt]);
        }

        float mb0 = -1e30f, mb1 = -1e30f;
        #pragma unroll
        for (int nt = 0; nt < 8; nt++) {
            const int kc = c * 64 + nt * 8 + (lane & 3) * 2;
            float2 bb0 = *(const float2*)&bias[(size_t)qr0 * S_ + kc];
            float2 bb1 = *(const float2*)&bias[(size_t)(qr0 + 8) * S_ + kc];
            sacc[nt][0] = sacc[nt][0] * isd + bb0.x;
            sacc[nt][1] = sacc[nt][1] * isd + bb0.y;
            sacc[nt][2] = sacc[nt][2] * isd + bb1.x;
            sacc[nt][3] = sacc[nt][3] * isd + bb1.y;
            mb0 = fmaxf(mb0, fmaxf(sacc[nt][0], sacc[nt][1]));
            mb1 = fmaxf(mb1, fmaxf(sacc[nt][2], sacc[nt][3]));
        }
        #pragma unroll
        for (int d = 1; d <= 2; d <<= 1) {
            mb0 = fmaxf(mb0, __shfl_xor_sync(0xffffffffu, mb0, d));
            mb1 = fmaxf(mb1, __shfl_xor_sync(0xffffffffu, mb1, d));
        }
        const float mn0 = fmaxf(mrow[0], mb0), mn1 = fmaxf(mrow[1], mb1);
        const float f0 = __expf(mrow[0] - mn0), f1 = __expf(mrow[1] - mn1);
        mrow[0] = mn0; mrow[1] = mn1;
        lrow[0] *= f0; lrow[1] *= f1;
        #pragma unroll
        for (int nt = 0; nt < 16; nt++) {
            acc_o[nt][0] *= f0; acc_o[nt][1] *= f0;
            acc_o[nt][2] *= f1; acc_o[nt][3] *= f1;
        }

        uint32_t ph[8][2];
        float ls0 = 0.f, ls1 = 0.f;
        #pragma unroll
        for (int nt = 0; nt < 8; nt++) {
            float p0 = __expf(sacc[nt][0] - mn0);
            float p1 = __expf(sacc[nt][1] - mn0);
            float p2 = __expf(sacc[nt][2] - mn1);
            float p3 = __expf(sacc[nt][3] - mn1);
            ls0 += p0 + p1; ls1 += p2 + p3;
            ph[nt][0] = h2u(__floats2half2_rn(p0, p1));
            ph[nt][1] = h2u(__floats2half2_rn(p2, p3));
        }
        #pragma unroll
        for (int d = 1; d <= 2; d <<= 1) {
            ls0 += __shfl_xor_sync(0xffffffffu, ls0, d);
            ls1 += __shfl_xor_sync(0xffffffffu, ls1, d);
        }
        lrow[0] += ls0; lrow[1] += ls1;

        #pragma unroll
        for (int kk = 0; kk < 4; kk++) {
            uint32_t af[4];
            af[0] = ph[2*kk][0]; af[1] = ph[2*kk][1];
            af[2] = ph[2*kk+1][0]; af[3] = ph[2*kk+1][1];
            #pragma unroll
            for (int p = 0; p < 8; p++) {
                uint32_t m4[4];
                ldsm_x4(m4, vb + (bRow + p * 16) * 144 + bColK + kk * 32);
                uint32_t bf0[2] = {m4[0], m4[1]};
                uint32_t bf1[2] = {m4[2], m4[3]};
                mma16(acc_o[2*p], af, bf0);
                mma16(acc_o[2*p+1], af, bf1);
            }
        }
        __syncthreads();
    }
    #undef ISSUE_KV

    const float inv0 = 1.f / lrow[0], inv1 = 1.f / lrow[1];
    h16* crow0 = ctx + (size_t)qr0 * D_ + h * DH_;
    h16* crow1 = crow0 + (size_t)8 * D_;
    #pragma unroll
    for (int nt = 0; nt < 16; nt++) {
        const int cc = nt * 8 + (lane & 3) * 2;
        *(__half2*)&crow0[cc] = __floats2half2_rn(acc_o[nt][0] * inv0, acc_o[nt][1] * inv0);
        *(__half2*)&crow1[cc] = __floats2half2_rn(acc_o[nt][2] * inv1, acc_o[nt][3] * inv1);
    }
}

// ---------- fast transpose-convert: [R][C] fp32 -> [C][R] fp16, 64x64 --------
__global__ __launch_bounds__(256) void tcvt64(
    const float* __restrict__ in, h16* __restrict__ out,
    int ldin, long long zin, int ldout, long long zout)
{
    __shared__ float sm[64][66];
    in  += (long long)blockIdx.z * zin;
    out += (long long)blockIdx.z * zout;
    int c0 = blockIdx.x * 64, r0 = blockIdx.y * 64;
    int tid = threadIdx.x;
    int lr = tid >> 4, lc4 = (tid & 15) * 4;
    #pragma unroll
    for (int i = 0; i < 4; i++) {
        float4 v = *(const float4*)&in[(long long)(r0 + lr + i*16) * ldin + c0 + lc4];
        sm[lr + i*16][lc4 + 0] = v.x; sm[lr + i*16][lc4 + 1] = v.y;
        sm[lr + i*16][lc4 + 2] = v.z; sm[lr + i*16][lc4 + 3] = v.w;
    }
    __syncthreads();
    int oc = tid >> 4, or4 = (tid & 15) * 4;
    #pragma unroll
    for (int i = 0; i < 4; i++) {
        int c = oc + i * 16;
        uint2 w;
        h16* wb = (h16*)&w;
        wb[0] = __float2half_rn(sm[or4 + 0][c]);
        wb[1] = __float2half_rn(sm[or4 + 1][c]);
        wb[2] = __float2half_rn(sm[or4 + 2][c]);
        wb[3] = __float2half_rn(sm[or4 + 3][c]);
        *(uint2*)&out[(long long)(c0 + c) * ldout + r0 + or4] = w;
    }
}

// ---------- h16 -> h16 transpose, 64x64 ---------------------------------------
__global__ __launch_bounds__(256) void tcvt16(
    const h16* __restrict__ in, h16* __restrict__ out,
    int ldin, long long zin, int ldout, long long zout)
{
    __shared__ h16 sm[64][68];
    in  += (long long)blockIdx.z * zin;
    out += (long long)blockIdx.z * zout;
    int c0 = blockIdx.x * 64, r0 = blockIdx.y * 64;
    int tid = threadIdx.x;
    int lr = tid >> 4, lc4 = (tid & 15) * 4;
    #pragma unroll
    for (int i = 0; i < 4; i++) {
        uint2 v = *(const uint2*)&in[(long long)(r0 + lr + i*16) * ldin + c0 + lc4];
        *(uint2*)&sm[lr + i*16][lc4] = v;
    }
    __syncthreads();
    int oc = tid >> 4, or4 = (tid & 15) * 4;
    #pragma unroll
    for (int i = 0; i < 4; i++) {
        int c = oc + i * 16;
        uint2 w;
        h16* wb = (h16*)&w;
        wb[0] = sm[or4 + 0][c]; wb[1] = sm[or4 + 1][c];
        wb[2] = sm[or4 + 2][c]; wb[3] = sm[or4 + 3][c];
        *(uint2*)&out[(long long)(c0 + c) * ldout + r0 + or4] = w;
    }
}

// ---------------- elementwise / reduction kernels ---------------------------
__global__ void reset_k() { int i = threadIdx.x; if (i < E_) g_cnt[i] = 0; }

__global__ void rmsnorm_k(const float* __restrict__ in, const float* __restrict__ w,
                          h16* __restrict__ outB, float* __restrict__ outRaw)
{
    int s = blockIdx.x;
    const float* x = in + (size_t)s * D_;
    float ss = 0.f;
    for (int d = threadIdx.x; d < D_; d += 256) { float v = x[d]; ss += v*v; }
    __shared__ float red[256];
    red[threadIdx.x] = ss; __syncthreads();
    for (int st = 128; st > 0; st >>= 1) {
        if (threadIdx.x < st) red[threadIdx.x] += red[threadIdx.x+st];
        __syncthreads();
    }
    float r = rsqrtf(red[0]/(float)D_ + EPS_);
    for (int d = threadIdx.x; d < D_; d += 256) {
        float v = x[d]*r*(1.f + w[d]);
        outB[(size_t)s*D_ + d] = __float2half_rn(v);
        if (outRaw) outRaw[(size_t)s*D_ + d] = v;
    }
}

__global__ void rope16_k(const h16* __restrict__ q, const h16* __restrict__ k,
                         h16* __restrict__ qo, h16* __restrict__ ko,
                         const float* __restrict__ cosp, const float* __restrict__ sinp)
{
    int idx = blockIdx.x*blockDim.x + threadIdx.x;
    if (idx >= S_*H_*64) return;
    int d = idx & 63;
    int h = (idx >> 6) & 15;
    int s = idx >> 10;
    float c1 = cosp[s*DH_ + d],      s1 = sinp[s*DH_ + d];
    float c2 = cosp[s*DH_ + d + 64], s2 = sinp[s*DH_ + d + 64];
    size_t base = (size_t)s*D_ + h*DH_ + d;
    float q1 = __half2float(q[base]), q2 = __half2float(q[base+64]);
    qo[base]    = __float2half_rn(q1*c1 - q2*s1);
    qo[base+64] = __float2half_rn(q2*c2 + q1*s2);
    float k1 = __half2float(k[base]), k2 = __half2float(k[base+64]);
    ko[base]    = __float2half_rn(k1*c1 - k2*s1);
    ko[base+64] = __float2half_rn(k2*c2 + k1*s2);
}

__global__ void sigmul16_k(const h16* __restrict__ ctx, const h16* __restrict__ gl,
                           h16* __restrict__ outp)
{
    int i = blockIdx.x*blockDim.x + threadIdx.x;
    if (i >= S_*D_) return;
    float g = __half2float(gl[i]);
    outp[i] = __float2half_rn(__half2float(ctx[i]) / (1.f + expf(-g)));
}

__global__ void silumul16_k(const h16* __restrict__ a, const h16* __restrict__ b,
                            h16* __restrict__ outp, int n)
{
    int i = blockIdx.x*blockDim.x + threadIdx.x;
    if (i >= n) return;
    float g = __half2float(a[i]);
    outp[i] = __float2half_rn(g / (1.f + expf(-g)) * __half2float(b[i]));
}

__global__ void router_k(const float* __restrict__ Y, const float* __restrict__ Rw)
{
    int t = blockIdx.x;
    int tid = threadIdx.x;
    float part[E_] = {};
    for (int d = tid; d < D_; d += 256) {
        float v = Y[(size_t)t*D_ + d];
        #pragma unroll
        for (int e = 0; e < E_; e++) part[e] += v * Rw[d*E_ + e];
    }
    __shared__ float red[256];
    __shared__ float logits[E_];
    for (int e = 0; e < E_; e++) {
        red[tid] = part[e]; __syncthreads();
        for (int st = 128; st > 0; st >>= 1) {
            if (tid < st) red[tid] += red[tid+st];
            __syncthreads();
        }
        if (tid == 0) logits[e] = red[0];
        __syncthreads();
    }
    if (tid == 0) {
        float m = -1e30f;
        for (int e = 0; e < E_; e++) m = fmaxf(m, logits[e]);
        float p[E_], s = 0.f;
        for (int e = 0; e < E_; e++) { p[e] = expf(logits[e]-m); s += p[e]; }
        for (int e = 0; e < E_; e++) p[e] /= s;
        int i0 = 0;
        for (int e = 1; e < E_; e++) if (p[e] > p[i0]) i0 = e;
        int i1 = (i0 == 0) ? 1 : 0;
        for (int e = 0; e < E_; e++) if (e != i0 && p[e] > p[i1]) i1 = e;
        float sum = p[i0] + p[i1];
        g_eidx[t*2]   = i0; g_eidx[t*2+1] = i1;
        g_ew[t*2]     = p[i0]/sum;
        g_ew[t*2+1]   = p[i1]/sum;
        atomicAdd(&g_cnt[i0], 1);
        atomicAdd(&g_cnt[i1], 1);
    }
}

__global__ void offsets_k()
{
    if (threadIdx.x == 0 && blockIdx.x == 0) {
        int acc = 0;
        for (int e = 0; e < E_; e++) { g_off[e] = acc; g_fill[e] = acc; acc += g_cnt[e]; }
        g_off[E_] = acc;
    }
}

__global__ void scatter_k()
{
    int t = blockIdx.x*blockDim.x + threadIdx.x;
    if (t >= S_) return;
    #pragma unroll
    for (int k = 0; k < 2; k++) {
        int e = g_eidx[t*2+k];
        int pos = atomicAdd(&g_fill[e], 1);
        g_perm[pos] = t;
        g_slot[t*2+k] = pos;
    }
}

__global__ void gsig_k(const float* __restrict__ Y, const float* __restrict__ gw)
{
    int t = blockIdx.x;
    float s = 0.f;
    for (int d = threadIdx.x; d < D_; d += 256) s += Y[(size_t)t*D_ + d] * gw[d];
    __shared__ float red[256];
    red[threadIdx.x] = s; __syncthreads();
    for (int st = 128; st > 0; st >>= 1) {
        if (threadIdx.x < st) red[threadIdx.x] += red[threadIdx.x+st];
        __syncthreads();
    }
    if (threadIdx.x == 0) g_gsig[t] = 1.f / (1.f + expf(-red[0]));
}

__global__ void final_k(float* __restrict__ out)
{
    int i = blockIdx.x*blockDim.x + threadIdx.x;
    if (i >= S_*D_) return;
    int t = i >> 11;
    int d = i & 2047;
    float m0 = g_ew[2*t]   * g_eo[(size_t)g_slot[2*t]  *D_ + d];
    float m1 = g_ew[2*t+1] * g_eo[(size_t)g_slot[2*t+1]*D_ + d];
    out[i] = g_hbuf[i] + m0 + m1 + g_shout[i]*g_gsig[t];
}

// ---------------- host launcher ---------------------------------------------
extern "C" void kernel_launch(void* const* d_in, const int* in_sizes, int n_in,
                              void* d_out, int out_size)
{
    const float* hidden = (const float*)d_in[0];
    const float* bias   = (const float*)d_in[1];
    const float* cosp   = (const float*)d_in[2];
    const float* sinp   = (const float*)d_in[3];
    const float* ln1w   = (const float*)d_in[4];
    const float* ln2w   = (const float*)d_in[5];
    const float* wq     = (const float*)d_in[6];
    const float* wk     = (const float*)d_in[7];
    const float* wv     = (const float*)d_in[8];
    const float* wg     = (const float*)d_in[9];
    const float* wo     = (const float*)d_in[10];
    const float* rw     = (const float*)d_in[11];
    const float* eg     = (const float*)d_in[12];
    const float* eu     = (const float*)d_in[13];
    const float* ed     = (const float*)d_in[14];
    const float* shg    = (const float*)d_in[15];
    const float* shu    = (const float*)d_in[16];
    const float* shd    = (const float*)d_in[17];
    const float* shgw   = (const float*)d_in[18];
    float* out = (float*)d_out;

    float *pq, *pk, *pv, *pgl, *pctx, *ph, *psgf, *pmactf, *pshout, *peo;
    cudaGetSymbolAddress((void**)&pq,    g_q);
    cudaGetSymbolAddress((void**)&pk,    g_k);
    cudaGetSymbolAddress((void**)&pv,    g_v);
    cudaGetSymbolAddress((void**)&pgl,   g_gl);
    cudaGetSymbolAddress((void**)&pctx,  g_ctx);
    cudaGetSymbolAddress((void**)&ph,    g_hbuf);
    cudaGetSymbolAddress((void**)&psgf,  g_sgf);
    cudaGetSymbolAddress((void**)&pmactf,g_mactf);
    cudaGetSymbolAddress((void**)&pshout,g_shout);
    cudaGetSymbolAddress((void**)&peo,   g_eo);

    h16 *bx, *bq, *bk, *bvT, *bup, *bctx, *by, *bsg, *bmact;
    h16 *Bwq, *Bwk, *Bwv, *Bwg, *Bwo, *Bshg, *Bshu, *Bshd, *Beg, *Beu, *Bed;
    cudaGetSymbolAddress((void**)&bx,   b_x);
    cudaGetSymbolAddress((void**)&bq,   b_q);
    cudaGetSymbolAddress((void**)&bk,   b_k);
    cudaGetSymbolAddress((void**)&bvT,  b_vT);
    cudaGetSymbolAddress((void**)&bup,  b_up);
    cudaGetSymbolAddress((void**)&bctx, b_ctx);
    cudaGetSymbolAddress((void**)&by,   b_y);
    cudaGetSymbolAddress((void**)&bsg,  b_sg);
    cudaGetSymbolAddress((void**)&bmact,b_mact);
    cudaGetSymbolAddress((void**)&Bwq,  b_wq);
    cudaGetSymbolAddress((void**)&Bwk,  b_wk);
    cudaGetSymbolAddress((void**)&Bwv,  b_wv);
    cudaGetSymbolAddress((void**)&Bwg,  b_wg);
    cudaGetSymbolAddress((void**)&Bwo,  b_wo);
    cudaGetSymbolAddress((void**)&Bshg, b_shg);
    cudaGetSymbolAddress((void**)&Bshu, b_shu);
    cudaGetSymbolAddress((void**)&Bshd, b_shd);
    cudaGetSymbolAddress((void**)&Beg,  b_eg);
    cudaGetSymbolAddress((void**)&Beu,  b_eu);
    cudaGetSymbolAddress((void**)&Bed,  b_ed);

    h16* pq16   = (h16*)pq;
    h16* pk16   = (h16*)pk;
    h16* pv16   = (h16*)pv;
    h16* pgl16  = (h16*)pgl;
    h16* pctx16 = (h16*)pctx;
    h16* psg16  = (h16*)psgf;
    h16* pmact16= (h16*)pmactf;
    float* pyraw = pctx;

    const int SMEM = 110592;
    cudaFuncSetAttribute(bgemm<0,0>, cudaFuncAttributeMaxDynamicSharedMemorySize, SMEM);
    cudaFuncSetAttribute(bgemm<0,1>, cudaFuncAttributeMaxDynamicSharedMemorySize, SMEM);
    cudaFuncSetAttribute(bgemm<1,1>, cudaFuncAttributeMaxDynamicSharedMemorySize, SMEM);
    cudaFuncSetAttribute(bgemm<2,0>, cudaFuncAttributeMaxDynamicSharedMemorySize, SMEM);
    const int SMEM_F = 17408 + 2*17408 + 2*18432;   // 89088
    cudaFuncSetAttribute(flash_k, cudaFuncAttributeMaxDynamicSharedMemorySize, SMEM_F);

    const float isd = 0.08838834764831845f;
    dim3 tb(32, 8);

    // side stream + fork/join events (created once; graph-capturable pattern)
    static cudaStream_t s2 = nullptr;
    static cudaEvent_t ev0 = nullptr, evA = nullptr, evO = nullptr, evM = nullptr;
    if (!s2) {
        cudaStreamCreateWithFlags(&s2, cudaStreamNonBlocking);
        cudaEventCreateWithFlags(&ev0, cudaEventDisableTiming);
        cudaEventCreateWithFlags(&evA, cudaEventDisableTiming);
        cudaEventCreateWithFlags(&evO, cudaEventDisableTiming);
        cudaEventCreateWithFlags(&evM, cudaEventDisableTiming);
    }

    // ---- fork: weight conversions on side stream ----
    cudaEventRecord(ev0, 0);
    cudaStreamWaitEvent(s2, ev0, 0);
    tcvt64<<<dim3(32,32), 256, 0, s2>>>(wq, Bwq, D_, 0, D_, 0);
    tcvt64<<<dim3(32,32), 256, 0, s2>>>(wk, Bwk, D_, 0, D_, 0);
    tcvt64<<<dim3(32,32), 256, 0, s2>>>(wv, Bwv, D_, 0, D_, 0);
    tcvt64<<<dim3(32,32), 256, 0, s2>>>(wg, Bwg, D_, 0, D_, 0);
    cudaEventRecord(evA, s2);
    tcvt64<<<dim3(32,32), 256, 0, s2>>>(wo, Bwo, D_, 0, D_, 0);
    cudaEventRecord(evO, s2);
    tcvt64<<<dim3(64,32), 256, 0, s2>>>(shg, Bshg, SFF_, 0, D_, 0);
    tcvt64<<<dim3(64,32), 256, 0, s2>>>(shu, Bshu, SFF_, 0, D_, 0);
    tcvt64<<<dim3(32,64), 256, 0, s2>>>(shd, Bshd, D_, 0, SFF_, 0);
    tcvt64<<<dim3(12,32,E_), 256, 0, s2>>>(eg, Beg, FF_, (long long)D_*FF_, D_, (long long)FF_*D_);
    tcvt64<<<dim3(12,32,E_), 256, 0, s2>>>(eu, Beu, FF_, (long long)D_*FF_, D_, (long long)FF_*D_);
    tcvt64<<<dim3(32,12,E_), 256, 0, s2>>>(ed, Bed, D_, (long long)FF_*D_, FF_, (long long)D_*FF_);
    cudaEventRecord(evM, s2);

    // ---- main stream: attention ----
    reset_k<<<1, 32>>>();
    rmsnorm_k<<<S_, 256>>>(hidden, ln1w, bx, nullptr);
    cudaStreamWaitEvent(0, evA, 0);
    {
        BC4 bc = {{Bwq, Bwk, Bwv, Bwg}, {(float*)pq16, (float*)pk16, (float*)pv16, (float*)pgl16}};
        bgemm<0,1><<<dim3(64,16), 256, SMEM>>>(bx, D_, 0, bc, D_, 0, D_, 0,
                                               nullptr, 0, 0, S_, 8192, D_, 1.f, 2048);
    }
    rope16_k<<<(S_*H_*64 + 255)/256, 256>>>(pq16, pk16, bq, bk, cosp, sinp);
    tcvt16<<<dim3(2,32,H_), 256>>>(pv16, bvT, D_, 128LL, S_, (long long)DH_*S_);

    flash_k<<<dim3(S_/64, H_), 128, SMEM_F>>>(bq, bk, bvT, bias, pctx16, isd);

    sigmul16_k<<<(S_*D_ + 255)/256, 256>>>(pctx16, pgl16, bctx);
    cudaStreamWaitEvent(0, evO, 0);
    {
        BC4 bc = {{Bwo, 0, 0, 0}, {ph, 0, 0, 0}};
        bgemm<0,0><<<dim3(16,16), 256, SMEM>>>(bctx, D_, 0, bc, D_, 0, D_, 0,
                                               hidden, D_, 0, S_, D_, D_, 1.f, 2048);
    }

    // ---- routing (raw fp32 y) ----
    rmsnorm_k<<<S_, 256>>>(ph, ln2w, by, pyraw);
    router_k<<<S_, 256>>>(pyraw, rw);
    offsets_k<<<1, 1>>>();
    scatter_k<<<(S_ + 255)/256, 256>>>();
    gsig_k<<<S_, 256>>>(pyraw, shgw);

    // ---- join MoE/shared weights, then FFN phase ----
    cudaStreamWaitEvent(0, evM, 0);
    {
        BC4 bc = {{Bshg, Bshu, 0, 0}, {(float*)psg16, (float*)bup, 0, 0}};
        bgemm<0,1><<<dim3(64,16), 256, SMEM>>>(by, D_, 0, bc, D_, 0, SFF_, 0,
                                               nullptr, 0, 0, S_, 8192, D_, 1.f, 4096);
    }
    silumul16_k<<<(S_*SFF_ + 255)/256, 256>>>(psg16, bup, bsg, S_*SFF_);
    {
        BC4 bc = {{Bshd, 0, 0, 0}, {pshout, 0, 0, 0}};
        bgemm<0,0><<<dim3(16,16), 256, SMEM>>>(bsg, SFF_, 0, bc, SFF_, 0, D_, 0,
                                               nullptr, 0, 0, S_, D_, SFF_, 1.f, 2048);
    }

    {
        BC4 bc = {{Beg, Beu, 0, 0}, {(float*)pmact16, (float*)bup, 0, 0}};
        bgemm<1,1><<<dim3(12,16,E_), 256, SMEM>>>(by, D_, 0, bc, D_, (long long)FF_*D_,
                                                  FF_, 0, nullptr, 0, 0,
                                                  0, 1536, D_, 1.f, 768);
    }
    silumul16_k<<<(S_*2*FF_ + 255)/256, 256>>>(pmact16, bup, bmact, S_*2*FF_);
    {
        BC4 bc = {{Bed, 0, 0, 0}, {peo, 0, 0, 0}};
        bgemm<2,0><<<dim3(16,16,E_), 256, SMEM>>>(bmact, FF_, 0, bc, FF_, (long long)D_*FF_,
                                                  D_, 0, nullptr, 0, 0,
                                                  0, D_, FF_, 1.f, 2048);
    }

    final_k<<<(S_*D_ + 255)/256, 256>>>(out);
}

// round 15
// speedup vs baseline: 1.1059x; 1.0226x over previous
#include <cuda_runtime.h>
#include <cuda_fp16.h>
#include <math.h>
#include <string.h>
#include <stdint.h>

#define S_   2048
#define D_   2048
#define H_   16
#define DH_  128
#define E_   8
#define FF_  768
#define SFF_ 4096
#define EPS_ 1e-6f

typedef __half h16;

// ---------------- fp32 scratch ----------------------------------------------
__device__ float g_q[S_*D_];                   // h16 qkvg temps
__device__ float g_k[S_*D_];
__device__ float g_v[S_*D_];
__device__ float g_gl[S_*D_];
__device__ float g_ctx[S_*D_];                 // h16 ctx, then raw fp32 y
__device__ float g_hbuf[S_*D_];
__device__ float g_sgf[S_*SFF_];               // h16 shared-gate out
__device__ float g_mactf[(size_t)S_*2*FF_];    // h16 moe-gate out
__device__ float g_shout[S_*D_];
__device__ float g_eo[(size_t)S_*2*D_];
__device__ float g_gsig[S_];
__device__ int   g_eidx[S_*2];
__device__ float g_ew[S_*2];
__device__ int   g_cnt[E_];
__device__ int   g_off[E_+1];
__device__ int   g_fill[E_];
__device__ int   g_perm[S_*2];
__device__ int   g_slot[S_*2];

// ---------------- fp16 scratch ----------------------------------------------
__device__ h16 b_x[S_*D_];
__device__ h16 b_q[S_*D_];
__device__ h16 b_k[S_*D_];
__device__ h16 b_vT[S_*D_];                    // [H][DH][S]
__device__ h16 b_up[S_*SFF_];                  // h16 "up" scratch (shared/moe)
__device__ h16 b_ctx[S_*D_];
__device__ h16 b_y[S_*D_];
__device__ h16 b_sg[S_*SFF_];
__device__ h16 b_mact[(size_t)S_*2*FF_];
// transposed fp16 weights (K-major: [N][K])
__device__ h16 b_wq[D_*D_];
__device__ h16 b_wk[D_*D_];
__device__ h16 b_wv[D_*D_];
__device__ h16 b_wg[D_*D_];
__device__ h16 b_wo[D_*D_];
__device__ h16 b_shg[(size_t)SFF_*D_];
__device__ h16 b_shu[(size_t)SFF_*D_];
__device__ h16 b_shd[(size_t)D_*SFF_];
__device__ h16 b_eg[(size_t)E_*FF_*D_];
__device__ h16 b_eu[(size_t)E_*FF_*D_];
__device__ h16 b_ed[(size_t)E_*D_*FF_];

// ================= PTX helpers ===============================================
__device__ __forceinline__ void cpasync16(uint32_t dst, const void* src) {
    asm volatile("cp.async.cg.shared.global [%0], [%1], 16;"
        :: "r"(dst), "l"((unsigned long long)__cvta_generic_to_global(src)));
}
__device__ __forceinline__ uint32_t smem_u32(const void* p) {
    uint32_t a;
    asm("{ .reg .u64 t; cvta.to.shared.u64 t, %1; cvt.u32.u64 %0, t; }" : "=r"(a) : "l"(p));
    return a;
}
__device__ __forceinline__ uint32_t h2u(__half2 h) {
    uint32_t u;
    memcpy(&u, &h, 4);
    return u;
}
__device__ __forceinline__ void mma16(float c[4], const uint32_t a[4], const uint32_t b[2]) {
    asm volatile("mma.sync.aligned.m16n8k16.row.col.f32.f16.f16.f32 "
        "{%0,%1,%2,%3}, {%4,%5,%6,%7}, {%8,%9}, {%0,%1,%2,%3};"
        : "+f"(c[0]), "+f"(c[1]), "+f"(c[2]), "+f"(c[3])
        : "r"(a[0]), "r"(a[1]), "r"(a[2]), "r"(a[3]), "r"(b[0]), "r"(b[1]));
}
__device__ __forceinline__ void ldsm_x4(uint32_t r[4], uint32_t addr) {
    asm volatile("ldmatrix.sync.aligned.m8n8.x4.shared.b16 {%0,%1,%2,%3}, [%4];"
        : "=r"(r[0]), "=r"(r[1]), "=r"(r[2]), "=r"(r[3]) : "r"(addr));
}

struct BC4 { const h16* B[4]; float* C[4]; };

// ================= fp16 mma.sync GEMM (round-10, unchanged) ==================
template<int MOE, int H16>
__global__ __launch_bounds__(256) void bgemm(
    const h16* __restrict__ A, long long lda, long long strideA,
    BC4 bc, long long ldb, long long strideB,
    long long ldc, long long strideC,
    const float* __restrict__ add_, long long ldadd, long long strideAdd,
    int M, int N, int K, float alpha, int splitN)
{
    int cnt = M, seg = 0;
    if (MOE) {
        int e = blockIdx.z;
        cnt = g_cnt[e]; seg = g_off[e];
        if ((int)(blockIdx.y * 128) >= cnt) return;
    }
    const int colTotal = blockIdx.x * 128;
    const int bi = colTotal / splitN;
    const int colBase = colTotal - bi * splitN;
    const h16* B = bc.B[bi];
    float* C = bc.C[bi];
    if (MOE) {
        B += (long long)blockIdx.z * strideB;
    } else {
        A += (long long)blockIdx.z * strideA;
        B += (long long)blockIdx.z * strideB;
        C += (long long)blockIdx.z * (H16 ? 0 : strideC);
        if (H16) C = (float*)((h16*)bc.C[bi] + (long long)blockIdx.z * strideC);
        if (add_) add_ += (long long)blockIdx.z * strideAdd;
    }
    const int rowBase = blockIdx.y * 128;

    extern __shared__ char smc[];
    const uint32_t s32 = smem_u32(smc);

    const int tid = threadIdx.x, lane = tid & 31, wid = tid >> 5;
    const int wm = wid & 3, wn = wid >> 2;

    const h16* aSrc[4]; uint32_t aOff[4];
    const h16* bSrc[4];
    #pragma unroll
    for (int i = 0; i < 4; i++) {
        int f = tid + i * 256;
        int row = f >> 3, ch = f & 7;
        int r = rowBase + row;
        long long arow;
        if (MOE == 1)      { int rr = min(r, cnt - 1); arow = g_perm[seg + rr]; }
        else if (MOE == 2) { int rr = min(r, cnt - 1); arow = seg + rr; }
        else               arow = r;
        aSrc[i] = A + arow * lda + ch * 8;
        aOff[i] = (uint32_t)(row * 144 + ch * 16);
        bSrc[i] = B + (long long)(colBase + row) * ldb + ch * 8;
    }

    uint32_t aLd[2], bLd[4];
    {
        int arow = wm * 32 + (lane & 7) + ((lane >> 3) & 1) * 8;
        uint32_t acol = ((lane >> 4) & 1) * 16;
        #pragma unroll
        for (int mt = 0; mt < 2; mt++)
            aLd[mt] = (uint32_t)((arow + mt * 16) * 144) + acol;
        int brow = wn * 64 + (lane & 7) + ((lane >> 4) & 1) * 8;
        uint32_t bcol = ((lane >> 3) & 1) * 16;
        #pragma unroll
        for (int p = 0; p < 4; p++)
            bLd[p] = (uint32_t)((brow + p * 16) * 144) + bcol;
    }

    float acc[2][8][4] = {};
    const int NC = K >> 6;

    #define ISSUE(c) do { \
        int _s = (c) % 3; \
        uint32_t _ab = s32 + (uint32_t)_s * 18432u; \
        uint32_t _bb = s32 + 55296u + (uint32_t)_s * 18432u; \
        _Pragma("unroll") \
        for (int _i = 0; _i < 4; _i++) { \
            cpasync16(_ab + aOff[_i], aSrc[_i] + (long long)(c) * 64); \
            cpasync16(_bb + aOff[_i], bSrc[_i] + (long long)(c) * 64); \
        } \
        asm volatile("cp.async.commit_group;"); \
    } while (0)

    ISSUE(0);
    if (NC > 1) ISSUE(1);
    for (int c = 0; c < NC; c++) {
        if (c + 1 < NC) asm volatile("cp.async.wait_group 1;");
        else            asm volatile("cp.async.wait_group 0;");
        __syncthreads();
        if (c + 2 < NC) ISSUE(c + 2);
        const uint32_t sAb = s32 + (uint32_t)(c % 3) * 18432u;
        const uint32_t sBb = s32 + 55296u + (uint32_t)(c % 3) * 18432u;
        #pragma unroll
        for (int kk = 0; kk < 4; kk++) {
            const uint32_t ko = (uint32_t)kk * 32u;
            uint32_t af[2][4];
            #pragma unroll
            for (int mt = 0; mt < 2; mt++)
                ldsm_x4(af[mt], sAb + aLd[mt] + ko);
            uint32_t bfr[8][2];
            #pragma unroll
            for (int p = 0; p < 4; p++) {
                uint32_t m[4];
                ldsm_x4(m, sBb + bLd[p] + ko);
                bfr[2*p][0]   = m[0]; bfr[2*p][1]   = m[1];
                bfr[2*p+1][0] = m[2]; bfr[2*p+1][1] = m[3];
            }
            #pragma unroll
            for (int mt = 0; mt < 2; mt++)
                #pragma unroll
                for (int nt = 0; nt < 8; nt++)
                    mma16(acc[mt][nt], af[mt], bfr[nt]);
        }
        __syncthreads();
    }
    #undef ISSUE

    #pragma unroll
    for (int mt = 0; mt < 2; mt++) {
        const int lr0 = rowBase + wm * 32 + mt * 16 + (lane >> 2);
        const int lr1 = lr0 + 8;
        const long long cr0 = MOE ? (long long)(seg + lr0) : (long long)lr0;
        const long long cr1 = MOE ? (long long)(seg + lr1) : (long long)lr1;
        const bool ok0 = MOE ? (lr0 < cnt) : true;
        const bool ok1 = MOE ? (lr1 < cnt) : true;
        #pragma unroll
        for (int nt = 0; nt < 8; nt++) {
            const int cc = colBase + wn * 64 + nt * 8 + (lane & 3) * 2;
            if (ok0) {
                float vx = alpha * acc[mt][nt][0], vy = alpha * acc[mt][nt][1];
                if (H16) {
                    __half2 h2 = __floats2half2_rn(vx, vy);
                    *(__half2*)&((h16*)C)[cr0 * ldc + cc] = h2;
                } else {
                    if (add_) {
                        float2 t = *(const float2*)&add_[(long long)lr0 * ldadd + cc];
                        vx += t.x; vy += t.y;
                    }
                    float2 v; v.x = vx; v.y = vy;
                    *(float2*)&C[cr0 * ldc + cc] = v;
                }
            }
            if (ok1) {
                float vx = alpha * acc[mt][nt][2], vy = alpha * acc[mt][nt][3];
                if (H16) {
                    __half2 h2 = __floats2half2_rn(vx, vy);
                    *(__half2*)&((h16*)C)[cr1 * ldc + cc] = h2;
                } else {
                    if (add_) {
                        float2 t = *(const float2*)&add_[(long long)lr1 * ldadd + cc];
                        vx += t.x; vy += t.y;
                    }
                    float2 v; v.x = vx; v.y = vy;
                    *(float2*)&C[cr1 * ldc + cc] = v;
                }
            }
        }
    }
}

// ================= flash attention (round-12 math; 2 CTAs/SM) =================
__global__ __launch_bounds__(128, 2) void flash_k(
    const h16* __restrict__ Q, const h16* __restrict__ Kt,
    const h16* __restrict__ VT, const float* __restrict__ bias,
    h16* __restrict__ ctx, float isd)
{
    const int h = blockIdx.y;
    const int qb = blockIdx.x;
    const int tid = threadIdx.x, lane = tid & 31, w = tid >> 5;

    extern __shared__ char smc[];
    const uint32_t s32 = smem_u32(smc);
    const uint32_t sQ = s32;
    const uint32_t sK = s32 + 17408u;
    const uint32_t sV = s32 + 52224u;

    const h16* Qg = Q + (size_t)(qb * 64) * D_ + h * DH_;
    const h16* Kg = Kt + h * DH_;
    const h16* Vg = VT + (size_t)h * DH_ * S_;

    #pragma unroll
    for (int i = 0; i < 8; i++) {
        int idx = tid + i * 128;
        int row = idx >> 4, ch = idx & 15;
        cpasync16(sQ + (uint32_t)(row * 272 + ch * 16), Qg + (size_t)row * D_ + ch * 8);
    }
    asm volatile("cp.async.commit_group;");

    #define ISSUE_KV(c) do { \
        uint32_t _kb = sK + (uint32_t)((c) & 1) * 17408u; \
        uint32_t _vb = sV + (uint32_t)((c) & 1) * 18432u; \
        _Pragma("unroll") \
        for (int _i = 0; _i < 8; _i++) { \
            int _idx = tid + _i * 128; \
            int _kr = _idx >> 4, _kc = _idx & 15; \
            cpasync16(_kb + (uint32_t)(_kr * 272 + _kc * 16), \
                      Kg + (size_t)((c) * 64 + _kr) * D_ + _kc * 8); \
            int _vr = _idx >> 3, _vc = _idx & 7; \
            cpasync16(_vb + (uint32_t)(_vr * 144 + _vc * 16), \
                      Vg + (size_t)_vr * S_ + (c) * 64 + _vc * 8); \
        } \
        asm volatile("cp.async.commit_group;"); \
    } while (0)

    ISSUE_KV(0);
    asm volatile("cp.async.wait_group 0;");
    __syncthreads();

    const uint32_t aBase = (uint32_t)((w * 16 + (lane & 7) + ((lane >> 3) & 1) * 8) * 272)
                         + ((lane >> 4) & 1) * 16;
    const uint32_t bRow  = (uint32_t)(((lane & 7) + ((lane >> 4) & 1) * 8));
    const uint32_t bColK = ((lane >> 3) & 1) * 16;

    uint32_t qf[8][4];
    #pragma unroll
    for (int kk = 0; kk < 8; kk++)
        ldsm_x4(qf[kk], sQ + aBase + kk * 32);

    float acc_o[16][4] = {};
    float mrow[2] = {-1e30f, -1e30f};
    float lrow[2] = {0.f, 0.f};

    const int qr0 = qb * 64 + w * 16 + (lane >> 2);
    const int NC = S_ / 64;

    for (int c = 0; c < NC; c++) {
        if (c + 1 < NC) { ISSUE_KV(c + 1); asm volatile("cp.async.wait_group 1;"); }
        else            { asm volatile("cp.async.wait_group 0;"); }
        __syncthreads();
        const uint32_t kb = sK + (uint32_t)(c & 1) * 17408u;
        const uint32_t vb = sV + (uint32_t)(c & 1) * 18432u;

        float sacc[8][4] = {};
        #pragma unroll
        for (int kk = 0; kk < 8; kk++) {
            uint32_t bfr[8][2];
            #pragma unroll
            for (int p = 0; p < 4; p++) {
                uint32_t m4[4];
                ldsm_x4(m4, kb + (bRow + p * 16) * 272 + bColK + kk * 32);
                bfr[2*p][0] = m4[0]; bfr[2*p][1] = m4[1];
                bfr[2*p+1][0] = m4[2]; bfr[2*p+1][1] = m4[3];
            }
            #pragma unroll
            for (int nt = 0; nt < 8; nt++)
                mma16(sacc[nt], qf[kk], bfr[nt]);
        }

        float mb0 = -1e30f, mb1 = -1e30f;
        #pragma unroll
        for (int nt = 0; nt < 8; nt++) {
            const int kc = c * 64 + nt * 8 + (lane & 3) * 2;
            float2 bb0 = *(const float2*)&bias[(size_t)qr0 * S_ + kc];
            float2 bb1 = *(const float2*)&bias[(size_t)(qr0 + 8) * S_ + kc];
            sacc[nt][0] = sacc[nt][0] * isd + bb0.x;
            sacc[nt][1] = sacc[nt][1] * isd + bb0.y;
            sacc[nt][2] = sacc[nt][2] * isd + bb1.x;
            sacc[nt][3] = sacc[nt][3] * isd + bb1.y;
            mb0 = fmaxf(mb0, fmaxf(sacc[nt][0], sacc[nt][1]));
            mb1 = fmaxf(mb1, fmaxf(sacc[nt][2], sacc[nt][3]));
        }
        #pragma unroll
        for (int d = 1; d <= 2; d <<= 1) {
            mb0 = fmaxf(mb0, __shfl_xor_sync(0xffffffffu, mb0, d));
            mb1 = fmaxf(mb1, __shfl_xor_sync(0xffffffffu, mb1, d));
        }
        const float mn0 = fmaxf(mrow[0], mb0), mn1 = fmaxf(mrow[1], mb1);
        const float f0 = __expf(mrow[0] - mn0), f1 = __expf(mrow[1] - mn1);
        mrow[0] = mn0; mrow[1] = mn1;
        lrow[0] *= f0; lrow[1] *= f1;
        #pragma unroll
        for (int nt = 0; nt < 16; nt++) {
            acc_o[nt][0] *= f0; acc_o[nt][1] *= f0;
            acc_o[nt][2] *= f1; acc_o[nt][3] *= f1;
        }

        uint32_t ph[8][2];
        float ls0 = 0.f, ls1 = 0.f;
        #pragma unroll
        for (int nt = 0; nt < 8; nt++) {
            float p0 = __expf(sacc[nt][0] - mn0);
            float p1 = __expf(sacc[nt][1] - mn0);
            float p2 = __expf(sacc[nt][2] - mn1);
            float p3 = __expf(sacc[nt][3] - mn1);
            ls0 += p0 + p1; ls1 += p2 + p3;
            ph[nt][0] = h2u(__floats2half2_rn(p0, p1));
            ph[nt][1] = h2u(__floats2half2_rn(p2, p3));
        }
        #pragma unroll
        for (int d = 1; d <= 2; d <<= 1) {
            ls0 += __shfl_xor_sync(0xffffffffu, ls0, d);
            ls1 += __shfl_xor_sync(0xffffffffu, ls1, d);
        }
        lrow[0] += ls0; lrow[1] += ls1;

        #pragma unroll
        for (int kk = 0; kk < 4; kk++) {
            uint32_t af[4];
            af[0] = ph[2*kk][0]; af[1] = ph[2*kk][1];
            af[2] = ph[2*kk+1][0]; af[3] = ph[2*kk+1][1];
            #pragma unroll
            for (int p = 0; p < 8; p++) {
                uint32_t m4[4];
                ldsm_x4(m4, vb + (bRow + p * 16) * 144 + bColK + kk * 32);
                uint32_t bf0[2] = {m4[0], m4[1]};
                uint32_t bf1[2] = {m4[2], m4[3]};
                mma16(acc_o[2*p], af, bf0);
                mma16(acc_o[2*p+1], af, bf1);
            }
        }
        __syncthreads();
    }
    #undef ISSUE_KV

    const float inv0 = 1.f / lrow[0], inv1 = 1.f / lrow[1];
    h16* crow0 = ctx + (size_t)qr0 * D_ + h * DH_;
    h16* crow1 = crow0 + (size_t)8 * D_;
    #pragma unroll
    for (int nt = 0; nt < 16; nt++) {
        const int cc = nt * 8 + (lane & 3) * 2;
        *(__half2*)&crow0[cc] = __floats2half2_rn(acc_o[nt][0] * inv0, acc_o[nt][1] * inv0);
        *(__half2*)&crow1[cc] = __floats2half2_rn(acc_o[nt][2] * inv1, acc_o[nt][3] * inv1);
    }
}

// ---------- fast transpose-convert: [R][C] fp32 -> [C][R] fp16, 64x64 --------
__global__ __launch_bounds__(256) void tcvt64(
    const float* __restrict__ in, h16* __restrict__ out,
    int ldin, long long zin, int ldout, long long zout)
{
    __shared__ float sm[64][66];
    in  += (long long)blockIdx.z * zin;
    out += (long long)blockIdx.z * zout;
    int c0 = blockIdx.x * 64, r0 = blockIdx.y * 64;
    int tid = threadIdx.x;
    int lr = tid >> 4, lc4 = (tid & 15) * 4;
    #pragma unroll
    for (int i = 0; i < 4; i++) {
        float4 v = *(const float4*)&in[(long long)(r0 + lr + i*16) * ldin + c0 + lc4];
        sm[lr + i*16][lc4 + 0] = v.x; sm[lr + i*16][lc4 + 1] = v.y;
        sm[lr + i*16][lc4 + 2] = v.z; sm[lr + i*16][lc4 + 3] = v.w;
    }
    __syncthreads();
    int oc = tid >> 4, or4 = (tid & 15) * 4;
    #pragma unroll
    for (int i = 0; i < 4; i++) {
        int c = oc + i * 16;
        uint2 w;
        h16* wb = (h16*)&w;
        wb[0] = __float2half_rn(sm[or4 + 0][c]);
        wb[1] = __float2half_rn(sm[or4 + 1][c]);
        wb[2] = __float2half_rn(sm[or4 + 2][c]);
        wb[3] = __float2half_rn(sm[or4 + 3][c]);
        *(uint2*)&out[(long long)(c0 + c) * ldout + r0 + or4] = w;
    }
}

// ---------- h16 -> h16 transpose, 64x64 ---------------------------------------
__global__ __launch_bounds__(256) void tcvt16(
    const h16* __restrict__ in, h16* __restrict__ out,
    int ldin, long long zin, int ldout, long long zout)
{
    __shared__ h16 sm[64][68];
    in  += (long long)blockIdx.z * zin;
    out += (long long)blockIdx.z * zout;
    int c0 = blockIdx.x * 64, r0 = blockIdx.y * 64;
    int tid = threadIdx.x;
    int lr = tid >> 4, lc4 = (tid & 15) * 4;
    #pragma unroll
    for (int i = 0; i < 4; i++) {
        uint2 v = *(const uint2*)&in[(long long)(r0 + lr + i*16) * ldin + c0 + lc4];
        *(uint2*)&sm[lr + i*16][lc4] = v;
    }
    __syncthreads();
    int oc = tid >> 4, or4 = (tid & 15) * 4;
    #pragma unroll
    for (int i = 0; i < 4; i++) {
        int c = oc + i * 16;
        uint2 w;
        h16* wb = (h16*)&w;
        wb[0] = sm[or4 + 0][c]; wb[1] = sm[or4 + 1][c];
        wb[2] = sm[or4 + 2][c]; wb[3] = sm[or4 + 3][c];
        *(uint2*)&out[(long long)(c0 + c) * ldout + r0 + or4] = w;
    }
}

// ---------------- elementwise / reduction kernels ---------------------------
__global__ void reset_k() { int i = threadIdx.x; if (i < E_) g_cnt[i] = 0; }

__global__ void rmsnorm_k(const float* __restrict__ in, const float* __restrict__ w,
                          h16* __restrict__ outB, float* __restrict__ outRaw)
{
    int s = blockIdx.x;
    const float* x = in + (size_t)s * D_;
    float ss = 0.f;
    for (int d = threadIdx.x; d < D_; d += 256) { float v = x[d]; ss += v*v; }
    __shared__ float red[256];
    red[threadIdx.x] = ss; __syncthreads();
    for (int st = 128; st > 0; st >>= 1) {
        if (threadIdx.x < st) red[threadIdx.x] += red[threadIdx.x+st];
        __syncthreads();
    }
    float r = rsqrtf(red[0]/(float)D_ + EPS_);
    for (int d = threadIdx.x; d < D_; d += 256) {
        float v = x[d]*r*(1.f + w[d]);
        outB[(size_t)s*D_ + d] = __float2half_rn(v);
        if (outRaw) outRaw[(size_t)s*D_ + d] = v;
    }
}

__global__ void rope16_k(const h16* __restrict__ q, const h16* __restrict__ k,
                         h16* __restrict__ qo, h16* __restrict__ ko,
                         const float* __restrict__ cosp, const float* __restrict__ sinp)
{
    int idx = blockIdx.x*blockDim.x + threadIdx.x;
    if (idx >= S_*H_*64) return;
    int d = idx & 63;
    int h = (idx >> 6) & 15;
    int s = idx >> 10;
    float c1 = cosp[s*DH_ + d],      s1 = sinp[s*DH_ + d];
    float c2 = cosp[s*DH_ + d + 64], s2 = sinp[s*DH_ + d + 64];
    size_t base = (size_t)s*D_ + h*DH_ + d;
    float q1 = __half2float(q[base]), q2 = __half2float(q[base+64]);
    qo[base]    = __float2half_rn(q1*c1 - q2*s1);
    qo[base+64] = __float2half_rn(q2*c2 + q1*s2);
    float k1 = __half2float(k[base]), k2 = __half2float(k[base+64]);
    ko[base]    = __float2half_rn(k1*c1 - k2*s1);
    ko[base+64] = __float2half_rn(k2*c2 + k1*s2);
}

__global__ void sigmul16_k(const h16* __restrict__ ctx, const h16* __restrict__ gl,
                           h16* __restrict__ outp)
{
    int i = blockIdx.x*blockDim.x + threadIdx.x;
    if (i >= S_*D_) return;
    float g = __half2float(gl[i]);
    outp[i] = __float2half_rn(__half2float(ctx[i]) / (1.f + expf(-g)));
}

__global__ void silumul16_k(const h16* __restrict__ a, const h16* __restrict__ b,
                            h16* __restrict__ outp, int n)
{
    int i = blockIdx.x*blockDim.x + threadIdx.x;
    if (i >= n) return;
    float g = __half2float(a[i]);
    outp[i] = __float2half_rn(g / (1.f + expf(-g)) * __half2float(b[i]));
}

__global__ void router_k(const float* __restrict__ Y, const float* __restrict__ Rw)
{
    int t = blockIdx.x;
    int tid = threadIdx.x;
    float part[E_] = {};
    for (int d = tid; d < D_; d += 256) {
        float v = Y[(size_t)t*D_ + d];
        #pragma unroll
        for (int e = 0; e < E_; e++) part[e] += v * Rw[d*E_ + e];
    }
    __shared__ float red[256];
    __shared__ float logits[E_];
    for (int e = 0; e < E_; e++) {
        red[tid] = part[e]; __syncthreads();
        for (int st = 128; st > 0; st >>= 1) {
            if (tid < st) red[tid] += red[tid+st];
            __syncthreads();
        }
        if (tid == 0) logits[e] = red[0];
        __syncthreads();
    }
    if (tid == 0) {
        float m = -1e30f;
        for (int e = 0; e < E_; e++) m = fmaxf(m, logits[e]);
        float p[E_], s = 0.f;
        for (int e = 0; e < E_; e++) { p[e] = expf(logits[e]-m); s += p[e]; }
        for (int e = 0; e < E_; e++) p[e] /= s;
        int i0 = 0;
        for (int e = 1; e < E_; e++) if (p[e] > p[i0]) i0 = e;
        int i1 = (i0 == 0) ? 1 : 0;
        for (int e = 0; e < E_; e++) if (e != i0 && p[e] > p[i1]) i1 = e;
        float sum = p[i0] + p[i1];
        g_eidx[t*2]   = i0; g_eidx[t*2+1] = i1;
        g_ew[t*2]     = p[i0]/sum;
        g_ew[t*2+1]   = p[i1]/sum;
        atomicAdd(&g_cnt[i0], 1);
        atomicAdd(&g_cnt[i1], 1);
    }
}

__global__ void offsets_k()
{
    if (threadIdx.x == 0 && blockIdx.x == 0) {
        int acc = 0;
        for (int e = 0; e < E_; e++) { g_off[e] = acc; g_fill[e] = acc; acc += g_cnt[e]; }
        g_off[E_] = acc;
    }
}

__global__ void scatter_k()
{
    int t = blockIdx.x*blockDim.x + threadIdx.x;
    if (t >= S_) return;
    #pragma unroll
    for (int k = 0; k < 2; k++) {
        int e = g_eidx[t*2+k];
        int pos = atomicAdd(&g_fill[e], 1);
        g_perm[pos] = t;
        g_slot[t*2+k] = pos;
    }
}

__global__ void gsig_k(const float* __restrict__ Y, const float* __restrict__ gw)
{
    int t = blockIdx.x;
    float s = 0.f;
    for (int d = threadIdx.x; d < D_; d += 256) s += Y[(size_t)t*D_ + d] * gw[d];
    __shared__ float red[256];
    red[threadIdx.x] = s; __syncthreads();
    for (int st = 128; st > 0; st >>= 1) {
        if (threadIdx.x < st) red[threadIdx.x] += red[threadIdx.x+st];
        __syncthreads();
    }
    if (threadIdx.x == 0) g_gsig[t] = 1.f / (1.f + expf(-red[0]));
}

__global__ void final_k(float* __restrict__ out)
{
    int i = blockIdx.x*blockDim.x + threadIdx.x;
    if (i >= S_*D_) return;
    int t = i >> 11;
    int d = i & 2047;
    float m0 = g_ew[2*t]   * g_eo[(size_t)g_slot[2*t]  *D_ + d];
    float m1 = g_ew[2*t+1] * g_eo[(size_t)g_slot[2*t+1]*D_ + d];
    out[i] = g_hbuf[i] + m0 + m1 + g_shout[i]*g_gsig[t];
}

// ---------------- host launcher ---------------------------------------------
extern "C" void kernel_launch(void* const* d_in, const int* in_sizes, int n_in,
                              void* d_out, int out_size)
{
    const float* hidden = (const float*)d_in[0];
    const float* bias   = (const float*)d_in[1];
    const float* cosp   = (const float*)d_in[2];
    const float* sinp   = (const float*)d_in[3];
    const float* ln1w   = (const float*)d_in[4];
    const float* ln2w   = (const float*)d_in[5];
    const float* wq     = (const float*)d_in[6];
    const float* wk     = (const float*)d_in[7];
    const float* wv     = (const float*)d_in[8];
    const float* wg     = (const float*)d_in[9];
    const float* wo     = (const float*)d_in[10];
    const float* rw     = (const float*)d_in[11];
    const float* eg     = (const float*)d_in[12];
    const float* eu     = (const float*)d_in[13];
    const float* ed     = (const float*)d_in[14];
    const float* shg    = (const float*)d_in[15];
    const float* shu    = (const float*)d_in[16];
    const float* shd    = (const float*)d_in[17];
    const float* shgw   = (const float*)d_in[18];
    float* out = (float*)d_out;

    float *pq, *pk, *pv, *pgl, *pctx, *ph, *psgf, *pmactf, *pshout, *peo;
    cudaGetSymbolAddress((void**)&pq,    g_q);
    cudaGetSymbolAddress((void**)&pk,    g_k);
    cudaGetSymbolAddress((void**)&pv,    g_v);
    cudaGetSymbolAddress((void**)&pgl,   g_gl);
    cudaGetSymbolAddress((void**)&pctx,  g_ctx);
    cudaGetSymbolAddress((void**)&ph,    g_hbuf);
    cudaGetSymbolAddress((void**)&psgf,  g_sgf);
    cudaGetSymbolAddress((void**)&pmactf,g_mactf);
    cudaGetSymbolAddress((void**)&pshout,g_shout);
    cudaGetSymbolAddress((void**)&peo,   g_eo);

    h16 *bx, *bq, *bk, *bvT, *bup, *bctx, *by, *bsg, *bmact;
    h16 *Bwq, *Bwk, *Bwv, *Bwg, *Bwo, *Bshg, *Bshu, *Bshd, *Beg, *Beu, *Bed;
    cudaGetSymbolAddress((void**)&bx,   b_x);
    cudaGetSymbolAddress((void**)&bq,   b_q);
    cudaGetSymbolAddress((void**)&bk,   b_k);
    cudaGetSymbolAddress((void**)&bvT,  b_vT);
    cudaGetSymbolAddress((void**)&bup,  b_up);
    cudaGetSymbolAddress((void**)&bctx, b_ctx);
    cudaGetSymbolAddress((void**)&by,   b_y);
    cudaGetSymbolAddress((void**)&bsg,  b_sg);
    cudaGetSymbolAddress((void**)&bmact,b_mact);
    cudaGetSymbolAddress((void**)&Bwq,  b_wq);
    cudaGetSymbolAddress((void**)&Bwk,  b_wk);
    cudaGetSymbolAddress((void**)&Bwv,  b_wv);
    cudaGetSymbolAddress((void**)&Bwg,  b_wg);
    cudaGetSymbolAddress((void**)&Bwo,  b_wo);
    cudaGetSymbolAddress((void**)&Bshg, b_shg);
    cudaGetSymbolAddress((void**)&Bshu, b_shu);
    cudaGetSymbolAddress((void**)&Bshd, b_shd);
    cudaGetSymbolAddress((void**)&Beg,  b_eg);
    cudaGetSymbolAddress((void**)&Beu,  b_eu);
    cudaGetSymbolAddress((void**)&Bed,  b_ed);

    h16* pq16   = (h16*)pq;
    h16* pk16   = (h16*)pk;
    h16* pv16   = (h16*)pv;
    h16* pgl16  = (h16*)pgl;
    h16* pctx16 = (h16*)pctx;
    h16* psg16  = (h16*)psgf;
    h16* pmact16= (h16*)pmactf;
    float* pyraw = pctx;

    const int SMEM = 110592;
    cudaFuncSetAttribute(bgemm<0,0>, cudaFuncAttributeMaxDynamicSharedMemorySize, SMEM);
    cudaFuncSetAttribute(bgemm<0,1>, cudaFuncAttributeMaxDynamicSharedMemorySize, SMEM);
    cudaFuncSetAttribute(bgemm<1,1>, cudaFuncAttributeMaxDynamicSharedMemorySize, SMEM);
    cudaFuncSetAttribute(bgemm<2,0>, cudaFuncAttributeMaxDynamicSharedMemorySize, SMEM);
    const int SMEM_F = 17408 + 2*17408 + 2*18432;   // 89088
    cudaFuncSetAttribute(flash_k, cudaFuncAttributeMaxDynamicSharedMemorySize, SMEM_F);

    const float isd = 0.08838834764831845f;

    // side stream + fork/join events (created once; graph-capturable pattern)
    static cudaStream_t s2 = nullptr;
    static cudaEvent_t ev0 = nullptr, evO = nullptr, evM = nullptr;
    if (!s2) {
        cudaStreamCreateWithFlags(&s2, cudaStreamNonBlocking);
        cudaEventCreateWithFlags(&ev0, cudaEventDisableTiming);
        cudaEventCreateWithFlags(&evO, cudaEventDisableTiming);
        cudaEventCreateWithFlags(&evM, cudaEventDisableTiming);
    }

    // ---- main stream: critical-path conversions first ----
    reset_k<<<1, 32>>>();
    tcvt64<<<dim3(32,32), 256>>>(wq, Bwq, D_, 0, D_, 0);
    tcvt64<<<dim3(32,32), 256>>>(wk, Bwk, D_, 0, D_, 0);
    tcvt64<<<dim3(32,32), 256>>>(wv, Bwv, D_, 0, D_, 0);
    tcvt64<<<dim3(32,32), 256>>>(wg, Bwg, D_, 0, D_, 0);
    rmsnorm_k<<<S_, 256>>>(hidden, ln1w, bx, nullptr);

    // ---- fork: non-critical conversions overlap attention ----
    cudaEventRecord(ev0, 0);
    cudaStreamWaitEvent(s2, ev0, 0);
    tcvt64<<<dim3(32,32), 256, 0, s2>>>(wo, Bwo, D_, 0, D_, 0);
    cudaEventRecord(evO, s2);
    tcvt64<<<dim3(64,32), 256, 0, s2>>>(shg, Bshg, SFF_, 0, D_, 0);
    tcvt64<<<dim3(64,32), 256, 0, s2>>>(shu, Bshu, SFF_, 0, D_, 0);
    tcvt64<<<dim3(32,64), 256, 0, s2>>>(shd, Bshd, D_, 0, SFF_, 0);
    tcvt64<<<dim3(12,32,E_), 256, 0, s2>>>(eg, Beg, FF_, (long long)D_*FF_, D_, (long long)FF_*D_);
    tcvt64<<<dim3(12,32,E_), 256, 0, s2>>>(eu, Beu, FF_, (long long)D_*FF_, D_, (long long)FF_*D_);
    tcvt64<<<dim3(32,12,E_), 256, 0, s2>>>(ed, Bed, D_, (long long)FF_*D_, FF_, (long long)D_*FF_);
    cudaEventRecord(evM, s2);

    // ---- attention ----
    {
        BC4 bc = {{Bwq, Bwk, Bwv, Bwg}, {(float*)pq16, (float*)pk16, (float*)pv16, (float*)pgl16}};
        bgemm<0,1><<<dim3(64,16), 256, SMEM>>>(bx, D_, 0, bc, D_, 0, D_, 0,
                                               nullptr, 0, 0, S_, 8192, D_, 1.f, 2048);
    }
    rope16_k<<<(S_*H_*64 + 255)/256, 256>>>(pq16, pk16, bq, bk, cosp, sinp);
    tcvt16<<<dim3(2,32,H_), 256>>>(pv16, bvT, D_, 128LL, S_, (long long)DH_*S_);

    flash_k<<<dim3(S_/64, H_), 128, SMEM_F>>>(bq, bk, bvT, bias, pctx16, isd);

    sigmul16_k<<<(S_*D_ + 255)/256, 256>>>(pctx16, pgl16, bctx);
    cudaStreamWaitEvent(0, evO, 0);
    {
        BC4 bc = {{Bwo, 0, 0, 0}, {ph, 0, 0, 0}};
        bgemm<0,0><<<dim3(16,16), 256, SMEM>>>(bctx, D_, 0, bc, D_, 0, D_, 0,
                                               hidden, D_, 0, S_, D_, D_, 1.f, 2048);
    }

    // ---- routing (raw fp32 y) ----
    rmsnorm_k<<<S_, 256>>>(ph, ln2w, by, pyraw);
    router_k<<<S_, 256>>>(pyraw, rw);
    offsets_k<<<1, 1>>>();
    scatter_k<<<(S_ + 255)/256, 256>>>();
    gsig_k<<<S_, 256>>>(pyraw, shgw);

    // ---- join MoE/shared weights, then FFN phase ----
    cudaStreamWaitEvent(0, evM, 0);
    {
        BC4 bc = {{Bshg, Bshu, 0, 0}, {(float*)psg16, (float*)bup, 0, 0}};
        bgemm<0,1><<<dim3(64,16), 256, SMEM>>>(by, D_, 0, bc, D_, 0, SFF_, 0,
                                               nullptr, 0, 0, S_, 8192, D_, 1.f, 4096);
    }
    silumul16_k<<<(S_*SFF_ + 255)/256, 256>>>(psg16, bup, bsg, S_*SFF_);
    {
        BC4 bc = {{Bshd, 0, 0, 0}, {pshout, 0, 0, 0}};
        bgemm<0,0><<<dim3(16,16), 256, SMEM>>>(bsg, SFF_, 0, bc, SFF_, 0, D_, 0,
                                               nullptr, 0, 0, S_, D_, SFF_, 1.f, 2048);
    }

    {
        BC4 bc = {{Beg, Beu, 0, 0}, {(float*)pmact16, (float*)bup, 0, 0}};
        bgemm<1,1><<<dim3(12,16,E_), 256, SMEM>>>(by, D_, 0, bc, D_, (long long)FF_*D_,
                                                  FF_, 0, nullptr, 0, 0,
                                                  0, 1536, D_, 1.f, 768);
    }
    silumul16_k<<<(S_*2*FF_ + 255)/256, 256>>>(pmact16, bup, bmact, S_*2*FF_);
    {
        BC4 bc = {{Bed, 0, 0, 0}, {peo, 0, 0, 0}};
        bgemm<2,0><<<dim3(16,16,E_), 256, SMEM>>>(bmact, FF_, 0, bc, FF_, (long long)D_*FF_,
                                                  D_, 0, nullptr, 0, 0,
                                                  0, D_, FF_, 1.f, 2048);
    }

    final_k<<<(S_*D_ + 255)/256, 256>>>(out);
}

// round 16
// speedup vs baseline: 1.1500x; 1.0398x over previous
#include <cuda_runtime.h>
#include <cuda_fp16.h>
#include <math.h>
#include <string.h>
#include <stdint.h>

#define S_   2048
#define D_   2048
#define H_   16
#define DH_  128
#define E_   8
#define FF_  768
#define SFF_ 4096
#define EPS_ 1e-6f

typedef __half h16;

// ---------------- fp32 scratch ----------------------------------------------
__device__ float g_q[S_*D_];                   // h16 qkvg temps
__device__ float g_k[S_*D_];
__device__ float g_v[S_*D_];
__device__ float g_gl[S_*D_];
__device__ float g_ctx[S_*D_];                 // h16 ctx, then raw fp32 y
__device__ float g_hbuf[S_*D_];
__device__ float g_sgf[S_*SFF_];               // h16 shared-gate out
__device__ float g_mactf[(size_t)S_*2*FF_];    // h16 moe-gate out
__device__ float g_shout[S_*D_];
__device__ float g_eo[(size_t)S_*2*D_];
__device__ float g_gsig[S_];
__device__ int   g_eidx[S_*2];
__device__ float g_ew[S_*2];
__device__ int   g_cnt[E_];
__device__ int   g_off[E_+1];
__device__ int   g_fill[E_];
__device__ int   g_perm[S_*2];
__device__ int   g_slot[S_*2];

// ---------------- fp16 scratch ----------------------------------------------
__device__ h16 b_x[S_*D_];
__device__ h16 b_q[S_*D_];
__device__ h16 b_k[S_*D_];
__device__ h16 b_vT[S_*D_];                    // [H][DH][S]
__device__ h16 b_up[S_*SFF_];                  // shared-expert up (s2 chain)
__device__ h16 b_up2[(size_t)S_*2*FF_];        // MoE up (main chain)
__device__ h16 b_ctx[S_*D_];
__device__ h16 b_y[S_*D_];
__device__ h16 b_sg[S_*SFF_];
__device__ h16 b_mact[(size_t)S_*2*FF_];
// transposed fp16 weights (K-major: [N][K])
__device__ h16 b_wq[D_*D_];
__device__ h16 b_wk[D_*D_];
__device__ h16 b_wv[D_*D_];
__device__ h16 b_wg[D_*D_];
__device__ h16 b_wo[D_*D_];
__device__ h16 b_shg[(size_t)SFF_*D_];
__device__ h16 b_shu[(size_t)SFF_*D_];
__device__ h16 b_shd[(size_t)D_*SFF_];
__device__ h16 b_eg[(size_t)E_*FF_*D_];
__device__ h16 b_eu[(size_t)E_*FF_*D_];
__device__ h16 b_ed[(size_t)E_*D_*FF_];

// ================= PTX helpers ===============================================
__device__ __forceinline__ void cpasync16(uint32_t dst, const void* src) {
    asm volatile("cp.async.cg.shared.global [%0], [%1], 16;"
        :: "r"(dst), "l"((unsigned long long)__cvta_generic_to_global(src)));
}
__device__ __forceinline__ uint32_t smem_u32(const void* p) {
    uint32_t a;
    asm("{ .reg .u64 t; cvta.to.shared.u64 t, %1; cvt.u32.u64 %0, t; }" : "=r"(a) : "l"(p));
    return a;
}
__device__ __forceinline__ uint32_t h2u(__half2 h) {
    uint32_t u;
    memcpy(&u, &h, 4);
    return u;
}
__device__ __forceinline__ void mma16(float c[4], const uint32_t a[4], const uint32_t b[2]) {
    asm volatile("mma.sync.aligned.m16n8k16.row.col.f32.f16.f16.f32 "
        "{%0,%1,%2,%3}, {%4,%5,%6,%7}, {%8,%9}, {%0,%1,%2,%3};"
        : "+f"(c[0]), "+f"(c[1]), "+f"(c[2]), "+f"(c[3])
        : "r"(a[0]), "r"(a[1]), "r"(a[2]), "r"(a[3]), "r"(b[0]), "r"(b[1]));
}
__device__ __forceinline__ void ldsm_x4(uint32_t r[4], uint32_t addr) {
    asm volatile("ldmatrix.sync.aligned.m8n8.x4.shared.b16 {%0,%1,%2,%3}, [%4];"
        : "=r"(r[0]), "=r"(r[1]), "=r"(r[2]), "=r"(r[3]) : "r"(addr));
}

struct BC4 { const h16* B[4]; float* C[4]; };

// ================= fp16 mma.sync GEMM (unchanged) =============================
template<int MOE, int H16>
__global__ __launch_bounds__(256) void bgemm(
    const h16* __restrict__ A, long long lda, long long strideA,
    BC4 bc, long long ldb, long long strideB,
    long long ldc, long long strideC,
    const float* __restrict__ add_, long long ldadd, long long strideAdd,
    int M, int N, int K, float alpha, int splitN)
{
    int cnt = M, seg = 0;
    if (MOE) {
        int e = blockIdx.z;
        cnt = g_cnt[e]; seg = g_off[e];
        if ((int)(blockIdx.y * 128) >= cnt) return;
    }
    const int colTotal = blockIdx.x * 128;
    const int bi = colTotal / splitN;
    const int colBase = colTotal - bi * splitN;
    const h16* B = bc.B[bi];
    float* C = bc.C[bi];
    if (MOE) {
        B += (long long)blockIdx.z * strideB;
    } else {
        A += (long long)blockIdx.z * strideA;
        B += (long long)blockIdx.z * strideB;
        C += (long long)blockIdx.z * (H16 ? 0 : strideC);
        if (H16) C = (float*)((h16*)bc.C[bi] + (long long)blockIdx.z * strideC);
        if (add_) add_ += (long long)blockIdx.z * strideAdd;
    }
    const int rowBase = blockIdx.y * 128;

    extern __shared__ char smc[];
    const uint32_t s32 = smem_u32(smc);

    const int tid = threadIdx.x, lane = tid & 31, wid = tid >> 5;
    const int wm = wid & 3, wn = wid >> 2;

    const h16* aSrc[4]; uint32_t aOff[4];
    const h16* bSrc[4];
    #pragma unroll
    for (int i = 0; i < 4; i++) {
        int f = tid + i * 256;
        int row = f >> 3, ch = f & 7;
        int r = rowBase + row;
        long long arow;
        if (MOE == 1)      { int rr = min(r, cnt - 1); arow = g_perm[seg + rr]; }
        else if (MOE == 2) { int rr = min(r, cnt - 1); arow = seg + rr; }
        else               arow = r;
        aSrc[i] = A + arow * lda + ch * 8;
        aOff[i] = (uint32_t)(row * 144 + ch * 16);
        bSrc[i] = B + (long long)(colBase + row) * ldb + ch * 8;
    }

    uint32_t aLd[2], bLd[4];
    {
        int arow = wm * 32 + (lane & 7) + ((lane >> 3) & 1) * 8;
        uint32_t acol = ((lane >> 4) & 1) * 16;
        #pragma unroll
        for (int mt = 0; mt < 2; mt++)
            aLd[mt] = (uint32_t)((arow + mt * 16) * 144) + acol;
        int brow = wn * 64 + (lane & 7) + ((lane >> 4) & 1) * 8;
        uint32_t bcol = ((lane >> 3) & 1) * 16;
        #pragma unroll
        for (int p = 0; p < 4; p++)
            bLd[p] = (uint32_t)((brow + p * 16) * 144) + bcol;
    }

    float acc[2][8][4] = {};
    const int NC = K >> 6;

    #define ISSUE(c) do { \
        int _s = (c) % 3; \
        uint32_t _ab = s32 + (uint32_t)_s * 18432u; \
        uint32_t _bb = s32 + 55296u + (uint32_t)_s * 18432u; \
        _Pragma("unroll") \
        for (int _i = 0; _i < 4; _i++) { \
            cpasync16(_ab + aOff[_i], aSrc[_i] + (long long)(c) * 64); \
            cpasync16(_bb + aOff[_i], bSrc[_i] + (long long)(c) * 64); \
        } \
        asm volatile("cp.async.commit_group;"); \
    } while (0)

    ISSUE(0);
    if (NC > 1) ISSUE(1);
    for (int c = 0; c < NC; c++) {
        if (c + 1 < NC) asm volatile("cp.async.wait_group 1;");
        else            asm volatile("cp.async.wait_group 0;");
        __syncthreads();
        if (c + 2 < NC) ISSUE(c + 2);
        const uint32_t sAb = s32 + (uint32_t)(c % 3) * 18432u;
        const uint32_t sBb = s32 + 55296u + (uint32_t)(c % 3) * 18432u;
        #pragma unroll
        for (int kk = 0; kk < 4; kk++) {
            const uint32_t ko = (uint32_t)kk * 32u;
            uint32_t af[2][4];
            #pragma unroll
            for (int mt = 0; mt < 2; mt++)
                ldsm_x4(af[mt], sAb + aLd[mt] + ko);
            uint32_t bfr[8][2];
            #pragma unroll
            for (int p = 0; p < 4; p++) {
                uint32_t m[4];
                ldsm_x4(m, sBb + bLd[p] + ko);
                bfr[2*p][0]   = m[0]; bfr[2*p][1]   = m[1];
                bfr[2*p+1][0] = m[2]; bfr[2*p+1][1] = m[3];
            }
            #pragma unroll
            for (int mt = 0; mt < 2; mt++)
                #pragma unroll
                for (int nt = 0; nt < 8; nt++)
                    mma16(acc[mt][nt], af[mt], bfr[nt]);
        }
        __syncthreads();
    }
    #undef ISSUE

    #pragma unroll
    for (int mt = 0; mt < 2; mt++) {
        const int lr0 = rowBase + wm * 32 + mt * 16 + (lane >> 2);
        const int lr1 = lr0 + 8;
        const long long cr0 = MOE ? (long long)(seg + lr0) : (long long)lr0;
        const long long cr1 = MOE ? (long long)(seg + lr1) : (long long)lr1;
        const bool ok0 = MOE ? (lr0 < cnt) : true;
        const bool ok1 = MOE ? (lr1 < cnt) : true;
        #pragma unroll
        for (int nt = 0; nt < 8; nt++) {
            const int cc = colBase + wn * 64 + nt * 8 + (lane & 3) * 2;
            if (ok0) {
                float vx = alpha * acc[mt][nt][0], vy = alpha * acc[mt][nt][1];
                if (H16) {
                    __half2 h2 = __floats2half2_rn(vx, vy);
                    *(__half2*)&((h16*)C)[cr0 * ldc + cc] = h2;
                } else {
                    if (add_) {
                        float2 t = *(const float2*)&add_[(long long)lr0 * ldadd + cc];
                        vx += t.x; vy += t.y;
                    }
                    float2 v; v.x = vx; v.y = vy;
                    *(float2*)&C[cr0 * ldc + cc] = v;
                }
            }
            if (ok1) {
                float vx = alpha * acc[mt][nt][2], vy = alpha * acc[mt][nt][3];
                if (H16) {
                    __half2 h2 = __floats2half2_rn(vx, vy);
                    *(__half2*)&((h16*)C)[cr1 * ldc + cc] = h2;
                } else {
                    if (add_) {
                        float2 t = *(const float2*)&add_[(long long)lr1 * ldadd + cc];
                        vx += t.x; vy += t.y;
                    }
                    float2 v; v.x = vx; v.y = vy;
                    *(float2*)&C[cr1 * ldc + cc] = v;
                }
            }
        }
    }
}

// ================= flash attention (2 CTAs/SM, unchanged math) ================
__global__ __launch_bounds__(128, 2) void flash_k(
    const h16* __restrict__ Q, const h16* __restrict__ Kt,
    const h16* __restrict__ VT, const float* __restrict__ bias,
    h16* __restrict__ ctx, float isd)
{
    const int h = blockIdx.y;
    const int qb = blockIdx.x;
    const int tid = threadIdx.x, lane = tid & 31, w = tid >> 5;

    extern __shared__ char smc[];
    const uint32_t s32 = smem_u32(smc);
    const uint32_t sQ = s32;
    const uint32_t sK = s32 + 17408u;
    const uint32_t sV = s32 + 52224u;

    const h16* Qg = Q + (size_t)(qb * 64) * D_ + h * DH_;
    const h16* Kg = Kt + h * DH_;
    const h16* Vg = VT + (size_t)h * DH_ * S_;

    #pragma unroll
    for (int i = 0; i < 8; i++) {
        int idx = tid + i * 128;
        int row = idx >> 4, ch = idx & 15;
        cpasync16(sQ + (uint32_t)(row * 272 + ch * 16), Qg + (size_t)row * D_ + ch * 8);
    }
    asm volatile("cp.async.commit_group;");

    #define ISSUE_KV(c) do { \
        uint32_t _kb = sK + (uint32_t)((c) & 1) * 17408u; \
        uint32_t _vb = sV + (uint32_t)((c) & 1) * 18432u; \
        _Pragma("unroll") \
        for (int _i = 0; _i < 8; _i++) { \
            int _idx = tid + _i * 128; \
            int _kr = _idx >> 4, _kc = _idx & 15; \
            cpasync16(_kb + (uint32_t)(_kr * 272 + _kc * 16), \
                      Kg + (size_t)((c) * 64 + _kr) * D_ + _kc * 8); \
            int _vr = _idx >> 3, _vc = _idx & 7; \
            cpasync16(_vb + (uint32_t)(_vr * 144 + _vc * 16), \
                      Vg + (size_t)_vr * S_ + (c) * 64 + _vc * 8); \
        } \
        asm volatile("cp.async.commit_group;"); \
    } while (0)

    ISSUE_KV(0);
    asm volatile("cp.async.wait_group 0;");
    __syncthreads();

    const uint32_t aBase = (uint32_t)((w * 16 + (lane & 7) + ((lane >> 3) & 1) * 8) * 272)
                         + ((lane >> 4) & 1) * 16;
    const uint32_t bRow  = (uint32_t)(((lane & 7) + ((lane >> 4) & 1) * 8));
    const uint32_t bColK = ((lane >> 3) & 1) * 16;

    uint32_t qf[8][4];
    #pragma unroll
    for (int kk = 0; kk < 8; kk++)
        ldsm_x4(qf[kk], sQ + aBase + kk * 32);

    float acc_o[16][4] = {};
    float mrow[2] = {-1e30f, -1e30f};
    float lrow[2] = {0.f, 0.f};

    const int qr0 = qb * 64 + w * 16 + (lane >> 2);
    const int NC = S_ / 64;

    for (int c = 0; c < NC; c++) {
        if (c + 1 < NC) { ISSUE_KV(c + 1); asm volatile("cp.async.wait_group 1;"); }
        else            { asm volatile("cp.async.wait_group 0;"); }
        __syncthreads();
        const uint32_t kb = sK + (uint32_t)(c & 1) * 17408u;
        const uint32_t vb = sV + (uint32_t)(c & 1) * 18432u;

        float sacc[8][4] = {};
        #pragma unroll
        for (int kk = 0; kk < 8; kk++) {
            uint32_t bfr[8][2];
            #pragma unroll
            for (int p = 0; p < 4; p++) {
                uint32_t m4[4];
                ldsm_x4(m4, kb + (bRow + p * 16) * 272 + bColK + kk * 32);
                bfr[2*p][0] = m4[0]; bfr[2*p][1] = m4[1];
                bfr[2*p+1][0] = m4[2]; bfr[2*p+1][1] = m4[3];
            }
            #pragma unroll
            for (int nt = 0; nt < 8; nt++)
                mma16(sacc[nt], qf[kk], bfr[nt]);
        }

        float mb0 = -1e30f, mb1 = -1e30f;
        #pragma unroll
        for (int nt = 0; nt < 8; nt++) {
            const int kc = c * 64 + nt * 8 + (lane & 3) * 2;
            float2 bb0 = *(const float2*)&bias[(size_t)qr0 * S_ + kc];
            float2 bb1 = *(const float2*)&bias[(size_t)(qr0 + 8) * S_ + kc];
            sacc[nt][0] = sacc[nt][0] * isd + bb0.x;
            sacc[nt][1] = sacc[nt][1] * isd + bb0.y;
            sacc[nt][2] = sacc[nt][2] * isd + bb1.x;
            sacc[nt][3] = sacc[nt][3] * isd + bb1.y;
            mb0 = fmaxf(mb0, fmaxf(sacc[nt][0], sacc[nt][1]));
            mb1 = fmaxf(mb1, fmaxf(sacc[nt][2], sacc[nt][3]));
        }
        #pragma unroll
        for (int d = 1; d <= 2; d <<= 1) {
            mb0 = fmaxf(mb0, __shfl_xor_sync(0xffffffffu, mb0, d));
            mb1 = fmaxf(mb1, __shfl_xor_sync(0xffffffffu, mb1, d));
        }
        const float mn0 = fmaxf(mrow[0], mb0), mn1 = fmaxf(mrow[1], mb1);
        const float f0 = __expf(mrow[0] - mn0), f1 = __expf(mrow[1] - mn1);
        mrow[0] = mn0; mrow[1] = mn1;
        lrow[0] *= f0; lrow[1] *= f1;
        #pragma unroll
        for (int nt = 0; nt < 16; nt++) {
            acc_o[nt][0] *= f0; acc_o[nt][1] *= f0;
            acc_o[nt][2] *= f1; acc_o[nt][3] *= f1;
        }

        uint32_t ph[8][2];
        float ls0 = 0.f, ls1 = 0.f;
        #pragma unroll
        for (int nt = 0; nt < 8; nt++) {
            float p0 = __expf(sacc[nt][0] - mn0);
            float p1 = __expf(sacc[nt][1] - mn0);
            float p2 = __expf(sacc[nt][2] - mn1);
            float p3 = __expf(sacc[nt][3] - mn1);
            ls0 += p0 + p1; ls1 += p2 + p3;
            ph[nt][0] = h2u(__floats2half2_rn(p0, p1));
            ph[nt][1] = h2u(__floats2half2_rn(p2, p3));
        }
        #pragma unroll
        for (int d = 1; d <= 2; d <<= 1) {
            ls0 += __shfl_xor_sync(0xffffffffu, ls0, d);
            ls1 += __shfl_xor_sync(0xffffffffu, ls1, d);
        }
        lrow[0] += ls0; lrow[1] += ls1;

        #pragma unroll
        for (int kk = 0; kk < 4; kk++) {
            uint32_t af[4];
            af[0] = ph[2*kk][0]; af[1] = ph[2*kk][1];
            af[2] = ph[2*kk+1][0]; af[3] = ph[2*kk+1][1];
            #pragma unroll
            for (int p = 0; p < 8; p++) {
                uint32_t m4[4];
                ldsm_x4(m4, vb + (bRow + p * 16) * 144 + bColK + kk * 32);
                uint32_t bf0[2] = {m4[0], m4[1]};
                uint32_t bf1[2] = {m4[2], m4[3]};
                mma16(acc_o[2*p], af, bf0);
                mma16(acc_o[2*p+1], af, bf1);
            }
        }
        __syncthreads();
    }
    #undef ISSUE_KV

    const float inv0 = 1.f / lrow[0], inv1 = 1.f / lrow[1];
    h16* crow0 = ctx + (size_t)qr0 * D_ + h * DH_;
    h16* crow1 = crow0 + (size_t)8 * D_;
    #pragma unroll
    for (int nt = 0; nt < 16; nt++) {
        const int cc = nt * 8 + (lane & 3) * 2;
        *(__half2*)&crow0[cc] = __floats2half2_rn(acc_o[nt][0] * inv0, acc_o[nt][1] * inv0);
        *(__half2*)&crow1[cc] = __floats2half2_rn(acc_o[nt][2] * inv1, acc_o[nt][3] * inv1);
    }
}

// ---------- fast transpose-convert: [R][C] fp32 -> [C][R] fp16, 64x64 --------
__global__ __launch_bounds__(256) void tcvt64(
    const float* __restrict__ in, h16* __restrict__ out,
    int ldin, long long zin, int ldout, long long zout)
{
    __shared__ float sm[64][66];
    in  += (long long)blockIdx.z * zin;
    out += (long long)blockIdx.z * zout;
    int c0 = blockIdx.x * 64, r0 = blockIdx.y * 64;
    int tid = threadIdx.x;
    int lr = tid >> 4, lc4 = (tid & 15) * 4;
    #pragma unroll
    for (int i = 0; i < 4; i++) {
        float4 v = *(const float4*)&in[(long long)(r0 + lr + i*16) * ldin + c0 + lc4];
        sm[lr + i*16][lc4 + 0] = v.x; sm[lr + i*16][lc4 + 1] = v.y;
        sm[lr + i*16][lc4 + 2] = v.z; sm[lr + i*16][lc4 + 3] = v.w;
    }
    __syncthreads();
    int oc = tid >> 4, or4 = (tid & 15) * 4;
    #pragma unroll
    for (int i = 0; i < 4; i++) {
        int c = oc + i * 16;
        uint2 w;
        h16* wb = (h16*)&w;
        wb[0] = __float2half_rn(sm[or4 + 0][c]);
        wb[1] = __float2half_rn(sm[or4 + 1][c]);
        wb[2] = __float2half_rn(sm[or4 + 2][c]);
        wb[3] = __float2half_rn(sm[or4 + 3][c]);
        *(uint2*)&out[(long long)(c0 + c) * ldout + r0 + or4] = w;
    }
}

// ---------- h16 -> h16 transpose, 64x64 ---------------------------------------
__global__ __launch_bounds__(256) void tcvt16(
    const h16* __restrict__ in, h16* __restrict__ out,
    int ldin, long long zin, int ldout, long long zout)
{
    __shared__ h16 sm[64][68];
    in  += (long long)blockIdx.z * zin;
    out += (long long)blockIdx.z * zout;
    int c0 = blockIdx.x * 64, r0 = blockIdx.y * 64;
    int tid = threadIdx.x;
    int lr = tid >> 4, lc4 = (tid & 15) * 4;
    #pragma unroll
    for (int i = 0; i < 4; i++) {
        uint2 v = *(const uint2*)&in[(long long)(r0 + lr + i*16) * ldin + c0 + lc4];
        *(uint2*)&sm[lr + i*16][lc4] = v;
    }
    __syncthreads();
    int oc = tid >> 4, or4 = (tid & 15) * 4;
    #pragma unroll
    for (int i = 0; i < 4; i++) {
        int c = oc + i * 16;
        uint2 w;
        h16* wb = (h16*)&w;
        wb[0] = sm[or4 + 0][c]; wb[1] = sm[or4 + 1][c];
        wb[2] = sm[or4 + 2][c]; wb[3] = sm[or4 + 3][c];
        *(uint2*)&out[(long long)(c0 + c) * ldout + r0 + or4] = w;
    }
}

// ---------------- elementwise / reduction kernels ---------------------------
__global__ void reset_k() { int i = threadIdx.x; if (i < E_) g_cnt[i] = 0; }

__global__ void rmsnorm_k(const float* __restrict__ in, const float* __restrict__ w,
                          h16* __restrict__ outB, float* __restrict__ outRaw)
{
    int s = blockIdx.x;
    const float* x = in + (size_t)s * D_;
    float ss = 0.f;
    for (int d = threadIdx.x; d < D_; d += 256) { float v = x[d]; ss += v*v; }
    __shared__ float red[256];
    red[threadIdx.x] = ss; __syncthreads();
    for (int st = 128; st > 0; st >>= 1) {
        if (threadIdx.x < st) red[threadIdx.x] += red[threadIdx.x+st];
        __syncthreads();
    }
    float r = rsqrtf(red[0]/(float)D_ + EPS_);
    for (int d = threadIdx.x; d < D_; d += 256) {
        float v = x[d]*r*(1.f + w[d]);
        outB[(size_t)s*D_ + d] = __float2half_rn(v);
        if (outRaw) outRaw[(size_t)s*D_ + d] = v;
    }
}

__global__ void rope16_k(const h16* __restrict__ q, const h16* __restrict__ k,
                         h16* __restrict__ qo, h16* __restrict__ ko,
                         const float* __restrict__ cosp, const float* __restrict__ sinp)
{
    int idx = blockIdx.x*blockDim.x + threadIdx.x;
    if (idx >= S_*H_*64) return;
    int d = idx & 63;
    int h = (idx >> 6) & 15;
    int s = idx >> 10;
    float c1 = cosp[s*DH_ + d],      s1 = sinp[s*DH_ + d];
    float c2 = cosp[s*DH_ + d + 64], s2 = sinp[s*DH_ + d + 64];
    size_t base = (size_t)s*D_ + h*DH_ + d;
    float q1 = __half2float(q[base]), q2 = __half2float(q[base+64]);
    qo[base]    = __float2half_rn(q1*c1 - q2*s1);
    qo[base+64] = __float2half_rn(q2*c2 + q1*s2);
    float k1 = __half2float(k[base]), k2 = __half2float(k[base+64]);
    ko[base]    = __float2half_rn(k1*c1 - k2*s1);
    ko[base+64] = __float2half_rn(k2*c2 + k1*s2);
}

__global__ void sigmul16_k(const h16* __restrict__ ctx, const h16* __restrict__ gl,
                           h16* __restrict__ outp)
{
    int i = blockIdx.x*blockDim.x + threadIdx.x;
    if (i >= S_*D_) return;
    float g = __half2float(gl[i]);
    outp[i] = __float2half_rn(__half2float(ctx[i]) / (1.f + expf(-g)));
}

__global__ void silumul16_k(const h16* __restrict__ a, const h16* __restrict__ b,
                            h16* __restrict__ outp, int n)
{
    int i = blockIdx.x*blockDim.x + threadIdx.x;
    if (i >= n) return;
    float g = __half2float(a[i]);
    outp[i] = __float2half_rn(g / (1.f + expf(-g)) * __half2float(b[i]));
}

// router + gsig fused: one streaming pass over raw fp32 y per token
__global__ void router_k(const float* __restrict__ Y, const float* __restrict__ Rw,
                         const float* __restrict__ gw)
{
    int t = blockIdx.x;
    int tid = threadIdx.x;
    float part[E_] = {};
    float gpart = 0.f;
    for (int d = tid; d < D_; d += 256) {
        float v = Y[(size_t)t*D_ + d];
        #pragma unroll
        for (int e = 0; e < E_; e++) part[e] += v * Rw[d*E_ + e];
        gpart += v * gw[d];
    }
    __shared__ float red[256];
    __shared__ float logits[E_];
    for (int e = 0; e < E_; e++) {
        red[tid] = part[e]; __syncthreads();
        for (int st = 128; st > 0; st >>= 1) {
            if (tid < st) red[tid] += red[tid+st];
            __syncthreads();
        }
        if (tid == 0) logits[e] = red[0];
        __syncthreads();
    }
    red[tid] = gpart; __syncthreads();
    for (int st = 128; st > 0; st >>= 1) {
        if (tid < st) red[tid] += red[tid+st];
        __syncthreads();
    }
    if (tid == 0) {
        g_gsig[t] = 1.f / (1.f + expf(-red[0]));
        float m = -1e30f;
        for (int e = 0; e < E_; e++) m = fmaxf(m, logits[e]);
        float p[E_], s = 0.f;
        for (int e = 0; e < E_; e++) { p[e] = expf(logits[e]-m); s += p[e]; }
        for (int e = 0; e < E_; e++) p[e] /= s;
        int i0 = 0;
        for (int e = 1; e < E_; e++) if (p[e] > p[i0]) i0 = e;
        int i1 = (i0 == 0) ? 1 : 0;
        for (int e = 0; e < E_; e++) if (e != i0 && p[e] > p[i1]) i1 = e;
        float sum = p[i0] + p[i1];
        g_eidx[t*2]   = i0; g_eidx[t*2+1] = i1;
        g_ew[t*2]     = p[i0]/sum;
        g_ew[t*2+1]   = p[i1]/sum;
        atomicAdd(&g_cnt[i0], 1);
        atomicAdd(&g_cnt[i1], 1);
    }
}

__global__ void offsets_k()
{
    if (threadIdx.x == 0 && blockIdx.x == 0) {
        int acc = 0;
        for (int e = 0; e < E_; e++) { g_off[e] = acc; g_fill[e] = acc; acc += g_cnt[e]; }
        g_off[E_] = acc;
    }
}

__global__ void scatter_k()
{
    int t = blockIdx.x*blockDim.x + threadIdx.x;
    if (t >= S_) return;
    #pragma unroll
    for (int k = 0; k < 2; k++) {
        int e = g_eidx[t*2+k];
        int pos = atomicAdd(&g_fill[e], 1);
        g_perm[pos] = t;
        g_slot[t*2+k] = pos;
    }
}

__global__ void final_k(float* __restrict__ out)
{
    int i = blockIdx.x*blockDim.x + threadIdx.x;
    if (i >= S_*D_) return;
    int t = i >> 11;
    int d = i & 2047;
    float m0 = g_ew[2*t]   * g_eo[(size_t)g_slot[2*t]  *D_ + d];
    float m1 = g_ew[2*t+1] * g_eo[(size_t)g_slot[2*t+1]*D_ + d];
    out[i] = g_hbuf[i] + m0 + m1 + g_shout[i]*g_gsig[t];
}

// ---------------- host launcher ---------------------------------------------
extern "C" void kernel_launch(void* const* d_in, const int* in_sizes, int n_in,
                              void* d_out, int out_size)
{
    const float* hidden = (const float*)d_in[0];
    const float* bias   = (const float*)d_in[1];
    const float* cosp   = (const float*)d_in[2];
    const float* sinp   = (const float*)d_in[3];
    const float* ln1w   = (const float*)d_in[4];
    const float* ln2w   = (const float*)d_in[5];
    const float* wq     = (const float*)d_in[6];
    const float* wk     = (const float*)d_in[7];
    const float* wv     = (const float*)d_in[8];
    const float* wg     = (const float*)d_in[9];
    const float* wo     = (const float*)d_in[10];
    const float* rw     = (const float*)d_in[11];
    const float* eg     = (const float*)d_in[12];
    const float* eu     = (const float*)d_in[13];
    const float* ed     = (const float*)d_in[14];
    const float* shg    = (const float*)d_in[15];
    const float* shu    = (const float*)d_in[16];
    const float* shd    = (const float*)d_in[17];
    const float* shgw   = (const float*)d_in[18];
    float* out = (float*)d_out;

    float *pq, *pk, *pv, *pgl, *pctx, *ph, *psgf, *pmactf, *pshout, *peo;
    cudaGetSymbolAddress((void**)&pq,    g_q);
    cudaGetSymbolAddress((void**)&pk,    g_k);
    cudaGetSymbolAddress((void**)&pv,    g_v);
    cudaGetSymbolAddress((void**)&pgl,   g_gl);
    cudaGetSymbolAddress((void**)&pctx,  g_ctx);
    cudaGetSymbolAddress((void**)&ph,    g_hbuf);
    cudaGetSymbolAddress((void**)&psgf,  g_sgf);
    cudaGetSymbolAddress((void**)&pmactf,g_mactf);
    cudaGetSymbolAddress((void**)&pshout,g_shout);
    cudaGetSymbolAddress((void**)&peo,   g_eo);

    h16 *bx, *bq, *bk, *bvT, *bup, *bup2, *bctx, *by, *bsg, *bmact;
    h16 *Bwq, *Bwk, *Bwv, *Bwg, *Bwo, *Bshg, *Bshu, *Bshd, *Beg, *Beu, *Bed;
    cudaGetSymbolAddress((void**)&bx,   b_x);
    cudaGetSymbolAddress((void**)&bq,   b_q);
    cudaGetSymbolAddress((void**)&bk,   b_k);
    cudaGetSymbolAddress((void**)&bvT,  b_vT);
    cudaGetSymbolAddress((void**)&bup,  b_up);
    cudaGetSymbolAddress((void**)&bup2, b_up2);
    cudaGetSymbolAddress((void**)&bctx, b_ctx);
    cudaGetSymbolAddress((void**)&by,   b_y);
    cudaGetSymbolAddress((void**)&bsg,  b_sg);
    cudaGetSymbolAddress((void**)&bmact,b_mact);
    cudaGetSymbolAddress((void**)&Bwq,  b_wq);
    cudaGetSymbolAddress((void**)&Bwk,  b_wk);
    cudaGetSymbolAddress((void**)&Bwv,  b_wv);
    cudaGetSymbolAddress((void**)&Bwg,  b_wg);
    cudaGetSymbolAddress((void**)&Bwo,  b_wo);
    cudaGetSymbolAddress((void**)&Bshg, b_shg);
    cudaGetSymbolAddress((void**)&Bshu, b_shu);
    cudaGetSymbolAddress((void**)&Bshd, b_shd);
    cudaGetSymbolAddress((void**)&Beg,  b_eg);
    cudaGetSymbolAddress((void**)&Beu,  b_eu);
    cudaGetSymbolAddress((void**)&Bed,  b_ed);

    h16* pq16   = (h16*)pq;
    h16* pk16   = (h16*)pk;
    h16* pv16   = (h16*)pv;
    h16* pgl16  = (h16*)pgl;
    h16* pctx16 = (h16*)pctx;
    h16* psg16  = (h16*)psgf;
    h16* pmact16= (h16*)pmactf;
    float* pyraw = pctx;

    const int SMEM = 110592;
    cudaFuncSetAttribute(bgemm<0,0>, cudaFuncAttributeMaxDynamicSharedMemorySize, SMEM);
    cudaFuncSetAttribute(bgemm<0,1>, cudaFuncAttributeMaxDynamicSharedMemorySize, SMEM);
    cudaFuncSetAttribute(bgemm<1,1>, cudaFuncAttributeMaxDynamicSharedMemorySize, SMEM);
    cudaFuncSetAttribute(bgemm<2,0>, cudaFuncAttributeMaxDynamicSharedMemorySize, SMEM);
    const int SMEM_F = 17408 + 2*17408 + 2*18432;   // 89088
    cudaFuncSetAttribute(flash_k, cudaFuncAttributeMaxDynamicSharedMemorySize, SMEM_F);

    const float isd = 0.08838834764831845f;

    // side stream + fork/join events (created once; graph-capturable pattern)
    static cudaStream_t s2 = nullptr;
    static cudaEvent_t ev0 = nullptr, evO = nullptr, evM = nullptr, evY = nullptr, evSH = nullptr;
    if (!s2) {
        cudaStreamCreateWithFlags(&s2, cudaStreamNonBlocking);
        cudaEventCreateWithFlags(&ev0, cudaEventDisableTiming);
        cudaEventCreateWithFlags(&evO, cudaEventDisableTiming);
        cudaEventCreateWithFlags(&evM, cudaEventDisableTiming);
        cudaEventCreateWithFlags(&evY, cudaEventDisableTiming);
        cudaEventCreateWithFlags(&evSH, cudaEventDisableTiming);
    }

    // ---- main stream: critical-path conversions first ----
    reset_k<<<1, 32>>>();
    tcvt64<<<dim3(32,32), 256>>>(wq, Bwq, D_, 0, D_, 0);
    tcvt64<<<dim3(32,32), 256>>>(wk, Bwk, D_, 0, D_, 0);
    tcvt64<<<dim3(32,32), 256>>>(wv, Bwv, D_, 0, D_, 0);
    tcvt64<<<dim3(32,32), 256>>>(wg, Bwg, D_, 0, D_, 0);
    rmsnorm_k<<<S_, 256>>>(hidden, ln1w, bx, nullptr);

    // ---- fork: non-critical conversions overlap attention ----
    cudaEventRecord(ev0, 0);
    cudaStreamWaitEvent(s2, ev0, 0);
    tcvt64<<<dim3(32,32), 256, 0, s2>>>(wo, Bwo, D_, 0, D_, 0);
    cudaEventRecord(evO, s2);
    tcvt64<<<dim3(64,32), 256, 0, s2>>>(shg, Bshg, SFF_, 0, D_, 0);
    tcvt64<<<dim3(64,32), 256, 0, s2>>>(shu, Bshu, SFF_, 0, D_, 0);
    tcvt64<<<dim3(32,64), 256, 0, s2>>>(shd, Bshd, D_, 0, SFF_, 0);
    tcvt64<<<dim3(12,32,E_), 256, 0, s2>>>(eg, Beg, FF_, (long long)D_*FF_, D_, (long long)FF_*D_);
    tcvt64<<<dim3(12,32,E_), 256, 0, s2>>>(eu, Beu, FF_, (long long)D_*FF_, D_, (long long)FF_*D_);
    tcvt64<<<dim3(32,12,E_), 256, 0, s2>>>(ed, Bed, D_, (long long)FF_*D_, FF_, (long long)D_*FF_);
    cudaEventRecord(evM, s2);

    // ---- attention (main) ----
    {
        BC4 bc = {{Bwq, Bwk, Bwv, Bwg}, {(float*)pq16, (float*)pk16, (float*)pv16, (float*)pgl16}};
        bgemm<0,1><<<dim3(64,16), 256, SMEM>>>(bx, D_, 0, bc, D_, 0, D_, 0,
                                               nullptr, 0, 0, S_, 8192, D_, 1.f, 2048);
    }
    rope16_k<<<(S_*H_*64 + 255)/256, 256>>>(pq16, pk16, bq, bk, cosp, sinp);
    tcvt16<<<dim3(2,32,H_), 256>>>(pv16, bvT, D_, 128LL, S_, (long long)DH_*S_);

    flash_k<<<dim3(S_/64, H_), 128, SMEM_F>>>(bq, bk, bvT, bias, pctx16, isd);

    sigmul16_k<<<(S_*D_ + 255)/256, 256>>>(pctx16, pgl16, bctx);
    cudaStreamWaitEvent(0, evO, 0);
    {
        BC4 bc = {{Bwo, 0, 0, 0}, {ph, 0, 0, 0}};
        bgemm<0,0><<<dim3(16,16), 256, SMEM>>>(bctx, D_, 0, bc, D_, 0, D_, 0,
                                               hidden, D_, 0, S_, D_, D_, 1.f, 2048);
    }

    // ---- y (main); fork shared-expert chain to s2 ----
    rmsnorm_k<<<S_, 256>>>(ph, ln2w, by, pyraw);
    cudaEventRecord(evY, 0);
    cudaStreamWaitEvent(s2, evY, 0);
    // shared expert on s2 (weights already converted on s2, same stream order)
    {
        BC4 bc = {{Bshg, Bshu, 0, 0}, {(float*)psg16, (float*)bup, 0, 0}};
        bgemm<0,1><<<dim3(64,16), 256, SMEM, s2>>>(by, D_, 0, bc, D_, 0, SFF_, 0,
                                                   nullptr, 0, 0, S_, 8192, D_, 1.f, 4096);
    }
    silumul16_k<<<(S_*SFF_ + 255)/256, 256, 0, s2>>>(psg16, bup, bsg, S_*SFF_);
    {
        BC4 bc = {{Bshd, 0, 0, 0}, {pshout, 0, 0, 0}};
        bgemm<0,0><<<dim3(16,16), 256, SMEM, s2>>>(bsg, SFF_, 0, bc, SFF_, 0, D_, 0,
                                                   nullptr, 0, 0, S_, D_, SFF_, 1.f, 2048);
    }
    cudaEventRecord(evSH, s2);

    // ---- routing (main, overlaps shared expert) ----
    router_k<<<S_, 256>>>(pyraw, rw, shgw);
    offsets_k<<<1, 1>>>();
    scatter_k<<<(S_ + 255)/256, 256>>>();

    // ---- MoE experts (main) ----
    cudaStreamWaitEvent(0, evM, 0);
    {
        BC4 bc = {{Beg, Beu, 0, 0}, {(float*)pmact16, (float*)bup2, 0, 0}};
        bgemm<1,1><<<dim3(12,16,E_), 256, SMEM>>>(by, D_, 0, bc, D_, (long long)FF_*D_,
                                                  FF_, 0, nullptr, 0, 0,
                                                  0, 1536, D_, 1.f, 768);
    }
    silumul16_k<<<(S_*2*FF_ + 255)/256, 256>>>(pmact16, bup2, bmact, S_*2*FF_);
    {
        BC4 bc = {{Bed, 0, 0, 0}, {peo, 0, 0, 0}};
        bgemm<2,0><<<dim3(16,16,E_), 256, SMEM>>>(bmact, FF_, 0, bc, FF_, (long long)D_*FF_,
                                                  D_, 0, nullptr, 0, 0,
                                                  0, D_, FF_, 1.f, 2048);
    }

    cudaStreamWaitEvent(0, evSH, 0);
    final_k<<<(S_*D_ + 255)/256, 256>>>(out);
}

// round 17
// speedup vs baseline: 1.1689x; 1.0165x over previous
#include <cuda_runtime.h>
#include <cuda_fp16.h>
#include <math.h>
#include <string.h>
#include <stdint.h>

#define S_   2048
#define D_   2048
#define H_   16
#define DH_  128
#define E_   8
#define FF_  768
#define SFF_ 4096
#define EPS_ 1e-6f

typedef __half h16;

// ---------------- fp32 scratch ----------------------------------------------
__device__ float g_q[S_*D_];
__device__ float g_k[S_*D_];
__device__ float g_v[S_*D_];
__device__ float g_gl[S_*D_];
__device__ float g_ctx[S_*D_];                 // h16 ctx, then raw fp32 y
__device__ float g_hbuf[S_*D_];
__device__ float g_sgf[S_*SFF_];
__device__ float g_mactf[(size_t)S_*2*FF_];
__device__ float g_shout[S_*D_];
__device__ float g_eo[(size_t)S_*2*D_];
__device__ float g_gsig[S_];
__device__ int   g_eidx[S_*2];
__device__ float g_ew[S_*2];
__device__ int   g_cnt[E_];
__device__ int   g_off[E_+1];
__device__ int   g_fill[E_];
__device__ int   g_perm[S_*2];
__device__ int   g_slot[S_*2];

// ---------------- fp16 scratch ----------------------------------------------
__device__ h16 b_x[S_*D_];
__device__ h16 b_q[S_*D_];
__device__ h16 b_k[S_*D_];
__device__ h16 b_vT[S_*D_];
__device__ h16 b_up[S_*SFF_];
__device__ h16 b_up2[(size_t)S_*2*FF_];
__device__ h16 b_ctx[S_*D_];
__device__ h16 b_y[S_*D_];
__device__ h16 b_sg[S_*SFF_];
__device__ h16 b_mact[(size_t)S_*2*FF_];
__device__ h16 b_wq[D_*D_];
__device__ h16 b_wk[D_*D_];
__device__ h16 b_wv[D_*D_];
__device__ h16 b_wg[D_*D_];
__device__ h16 b_wo[D_*D_];
__device__ h16 b_shg[(size_t)SFF_*D_];
__device__ h16 b_shu[(size_t)SFF_*D_];
__device__ h16 b_shd[(size_t)D_*SFF_];
__device__ h16 b_eg[(size_t)E_*FF_*D_];
__device__ h16 b_eu[(size_t)E_*FF_*D_];
__device__ h16 b_ed[(size_t)E_*D_*FF_];

// ================= PTX helpers ===============================================
__device__ __forceinline__ void cpasync16(uint32_t dst, const void* src) {
    asm volatile("cp.async.cg.shared.global [%0], [%1], 16;"
        :: "r"(dst), "l"((unsigned long long)__cvta_generic_to_global(src)));
}
__device__ __forceinline__ uint32_t smem_u32(const void* p) {
    uint32_t a;
    asm("{ .reg .u64 t; cvta.to.shared.u64 t, %1; cvt.u32.u64 %0, t; }" : "=r"(a) : "l"(p));
    return a;
}
__device__ __forceinline__ uint32_t h2u(__half2 h) {
    uint32_t u;
    memcpy(&u, &h, 4);
    return u;
}
__device__ __forceinline__ void mma16(float c[4], const uint32_t a[4], const uint32_t b[2]) {
    asm volatile("mma.sync.aligned.m16n8k16.row.col.f32.f16.f16.f32 "
        "{%0,%1,%2,%3}, {%4,%5,%6,%7}, {%8,%9}, {%0,%1,%2,%3};"
        : "+f"(c[0]), "+f"(c[1]), "+f"(c[2]), "+f"(c[3])
        : "r"(a[0]), "r"(a[1]), "r"(a[2]), "r"(a[3]), "r"(b[0]), "r"(b[1]));
}
__device__ __forceinline__ void ldsm_x4(uint32_t r[4], uint32_t addr) {
    asm volatile("ldmatrix.sync.aligned.m8n8.x4.shared.b16 {%0,%1,%2,%3}, [%4];"
        : "=r"(r[0]), "=r"(r[1]), "=r"(r[2]), "=r"(r[3]) : "r"(addr));
}

struct BC4 { const h16* B[4]; float* C[4]; };
struct P4  { const float* in[4]; h16* out[4]; };

// ================= fp16 mma.sync GEMM (unchanged) =============================
template<int MOE, int H16>
__global__ __launch_bounds__(256) void bgemm(
    const h16* __restrict__ A, long long lda, long long strideA,
    BC4 bc, long long ldb, long long strideB,
    long long ldc, long long strideC,
    const float* __restrict__ add_, long long ldadd, long long strideAdd,
    int M, int N, int K, float alpha, int splitN)
{
    int cnt = M, seg = 0;
    if (MOE) {
        int e = blockIdx.z;
        cnt = g_cnt[e]; seg = g_off[e];
        if ((int)(blockIdx.y * 128) >= cnt) return;
    }
    const int colTotal = blockIdx.x * 128;
    const int bi = colTotal / splitN;
    const int colBase = colTotal - bi * splitN;
    const h16* B = bc.B[bi];
    float* C = bc.C[bi];
    if (MOE) {
        B += (long long)blockIdx.z * strideB;
    } else {
        A += (long long)blockIdx.z * strideA;
        B += (long long)blockIdx.z * strideB;
        C += (long long)blockIdx.z * (H16 ? 0 : strideC);
        if (H16) C = (float*)((h16*)bc.C[bi] + (long long)blockIdx.z * strideC);
        if (add_) add_ += (long long)blockIdx.z * strideAdd;
    }
    const int rowBase = blockIdx.y * 128;

    extern __shared__ char smc[];
    const uint32_t s32 = smem_u32(smc);

    const int tid = threadIdx.x, lane = tid & 31, wid = tid >> 5;
    const int wm = wid & 3, wn = wid >> 2;

    const h16* aSrc[4]; uint32_t aOff[4];
    const h16* bSrc[4];
    #pragma unroll
    for (int i = 0; i < 4; i++) {
        int f = tid + i * 256;
        int row = f >> 3, ch = f & 7;
        int r = rowBase + row;
        long long arow;
        if (MOE == 1)      { int rr = min(r, cnt - 1); arow = g_perm[seg + rr]; }
        else if (MOE == 2) { int rr = min(r, cnt - 1); arow = seg + rr; }
        else               arow = r;
        aSrc[i] = A + arow * lda + ch * 8;
        aOff[i] = (uint32_t)(row * 144 + ch * 16);
        bSrc[i] = B + (long long)(colBase + row) * ldb + ch * 8;
    }

    uint32_t aLd[2], bLd[4];
    {
        int arow = wm * 32 + (lane & 7) + ((lane >> 3) & 1) * 8;
        uint32_t acol = ((lane >> 4) & 1) * 16;
        #pragma unroll
        for (int mt = 0; mt < 2; mt++)
            aLd[mt] = (uint32_t)((arow + mt * 16) * 144) + acol;
        int brow = wn * 64 + (lane & 7) + ((lane >> 4) & 1) * 8;
        uint32_t bcol = ((lane >> 3) & 1) * 16;
        #pragma unroll
        for (int p = 0; p < 4; p++)
            bLd[p] = (uint32_t)((brow + p * 16) * 144) + bcol;
    }

    float acc[2][8][4] = {};
    const int NC = K >> 6;

    #define ISSUE(c) do { \
        int _s = (c) % 3; \
        uint32_t _ab = s32 + (uint32_t)_s * 18432u; \
        uint32_t _bb = s32 + 55296u + (uint32_t)_s * 18432u; \
        _Pragma("unroll") \
        for (int _i = 0; _i < 4; _i++) { \
            cpasync16(_ab + aOff[_i], aSrc[_i] + (long long)(c) * 64); \
            cpasync16(_bb + aOff[_i], bSrc[_i] + (long long)(c) * 64); \
        } \
        asm volatile("cp.async.commit_group;"); \
    } while (0)

    ISSUE(0);
    if (NC > 1) ISSUE(1);
    for (int c = 0; c < NC; c++) {
        if (c + 1 < NC) asm volatile("cp.async.wait_group 1;");
        else            asm volatile("cp.async.wait_group 0;");
        __syncthreads();
        if (c + 2 < NC) ISSUE(c + 2);
        const uint32_t sAb = s32 + (uint32_t)(c % 3) * 18432u;
        const uint32_t sBb = s32 + 55296u + (uint32_t)(c % 3) * 18432u;
        #pragma unroll
        for (int kk = 0; kk < 4; kk++) {
            const uint32_t ko = (uint32_t)kk * 32u;
            uint32_t af[2][4];
            #pragma unroll
            for (int mt = 0; mt < 2; mt++)
                ldsm_x4(af[mt], sAb + aLd[mt] + ko);
            uint32_t bfr[8][2];
            #pragma unroll
            for (int p = 0; p < 4; p++) {
                uint32_t m[4];
                ldsm_x4(m, sBb + bLd[p] + ko);
                bfr[2*p][0]   = m[0]; bfr[2*p][1]   = m[1];
                bfr[2*p+1][0] = m[2]; bfr[2*p+1][1] = m[3];
            }
            #pragma unroll
            for (int mt = 0; mt < 2; mt++)
                #pragma unroll
                for (int nt = 0; nt < 8; nt++)
                    mma16(acc[mt][nt], af[mt], bfr[nt]);
        }
        __syncthreads();
    }
    #undef ISSUE

    #pragma unroll
    for (int mt = 0; mt < 2; mt++) {
        const int lr0 = rowBase + wm * 32 + mt * 16 + (lane >> 2);
        const int lr1 = lr0 + 8;
        const long long cr0 = MOE ? (long long)(seg + lr0) : (long long)lr0;
        const long long cr1 = MOE ? (long long)(seg + lr1) : (long long)lr1;
        const bool ok0 = MOE ? (lr0 < cnt) : true;
        const bool ok1 = MOE ? (lr1 < cnt) : true;
        #pragma unroll
        for (int nt = 0; nt < 8; nt++) {
            const int cc = colBase + wn * 64 + nt * 8 + (lane & 3) * 2;
            if (ok0) {
                float vx = alpha * acc[mt][nt][0], vy = alpha * acc[mt][nt][1];
                if (H16) {
                    __half2 h2 = __floats2half2_rn(vx, vy);
                    *(__half2*)&((h16*)C)[cr0 * ldc + cc] = h2;
                } else {
                    if (add_) {
                        float2 t = *(const float2*)&add_[(long long)lr0 * ldadd + cc];
                        vx += t.x; vy += t.y;
                    }
                    float2 v; v.x = vx; v.y = vy;
                    *(float2*)&C[cr0 * ldc + cc] = v;
                }
            }
            if (ok1) {
                float vx = alpha * acc[mt][nt][2], vy = alpha * acc[mt][nt][3];
                if (H16) {
                    __half2 h2 = __floats2half2_rn(vx, vy);
                    *(__half2*)&((h16*)C)[cr1 * ldc + cc] = h2;
                } else {
                    if (add_) {
                        float2 t = *(const float2*)&add_[(long long)lr1 * ldadd + cc];
                        vx += t.x; vy += t.y;
                    }
                    float2 v; v.x = vx; v.y = vy;
                    *(float2*)&C[cr1 * ldc + cc] = v;
                }
            }
        }
    }
}

// ================= flash attention (2 CTAs/SM, unchanged) =====================
__global__ __launch_bounds__(128, 2) void flash_k(
    const h16* __restrict__ Q, const h16* __restrict__ Kt,
    const h16* __restrict__ VT, const float* __restrict__ bias,
    h16* __restrict__ ctx, float isd)
{
    const int h = blockIdx.y;
    const int qb = blockIdx.x;
    const int tid = threadIdx.x, lane = tid & 31, w = tid >> 5;

    extern __shared__ char smc[];
    const uint32_t s32 = smem_u32(smc);
    const uint32_t sQ = s32;
    const uint32_t sK = s32 + 17408u;
    const uint32_t sV = s32 + 52224u;

    const h16* Qg = Q + (size_t)(qb * 64) * D_ + h * DH_;
    const h16* Kg = Kt + h * DH_;
    const h16* Vg = VT + (size_t)h * DH_ * S_;

    #pragma unroll
    for (int i = 0; i < 8; i++) {
        int idx = tid + i * 128;
        int row = idx >> 4, ch = idx & 15;
        cpasync16(sQ + (uint32_t)(row * 272 + ch * 16), Qg + (size_t)row * D_ + ch * 8);
    }
    asm volatile("cp.async.commit_group;");

    #define ISSUE_KV(c) do { \
        uint32_t _kb = sK + (uint32_t)((c) & 1) * 17408u; \
        uint32_t _vb = sV + (uint32_t)((c) & 1) * 18432u; \
        _Pragma("unroll") \
        for (int _i = 0; _i < 8; _i++) { \
            int _idx = tid + _i * 128; \
            int _kr = _idx >> 4, _kc = _idx & 15; \
            cpasync16(_kb + (uint32_t)(_kr * 272 + _kc * 16), \
                      Kg + (size_t)((c) * 64 + _kr) * D_ + _kc * 8); \
            int _vr = _idx >> 3, _vc = _idx & 7; \
            cpasync16(_vb + (uint32_t)(_vr * 144 + _vc * 16), \
                      Vg + (size_t)_vr * S_ + (c) * 64 + _vc * 8); \
        } \
        asm volatile("cp.async.commit_group;"); \
    } while (0)

    ISSUE_KV(0);
    asm volatile("cp.async.wait_group 0;");
    __syncthreads();

    const uint32_t aBase = (uint32_t)((w * 16 + (lane & 7) + ((lane >> 3) & 1) * 8) * 272)
                         + ((lane >> 4) & 1) * 16;
    const uint32_t bRow  = (uint32_t)(((lane & 7) + ((lane >> 4) & 1) * 8));
    const uint32_t bColK = ((lane >> 3) & 1) * 16;

    uint32_t qf[8][4];
    #pragma unroll
    for (int kk = 0; kk < 8; kk++)
        ldsm_x4(qf[kk], sQ + aBase + kk * 32);

    float acc_o[16][4] = {};
    float mrow[2] = {-1e30f, -1e30f};
    float lrow[2] = {0.f, 0.f};

    const int qr0 = qb * 64 + w * 16 + (lane >> 2);
    const int NC = S_ / 64;

    for (int c = 0; c < NC; c++) {
        if (c + 1 < NC) { ISSUE_KV(c + 1); asm volatile("cp.async.wait_group 1;"); }
        else            { asm volatile("cp.async.wait_group 0;"); }
        __syncthreads();
        const uint32_t kb = sK + (uint32_t)(c & 1) * 17408u;
        const uint32_t vb = sV + (uint32_t)(c & 1) * 18432u;

        float sacc[8][4] = {};
        #pragma unroll
        for (int kk = 0; kk < 8; kk++) {
            uint32_t bfr[8][2];
            #pragma unroll
            for (int p = 0; p < 4; p++) {
                uint32_t m4[4];
                ldsm_x4(m4, kb + (bRow + p * 16) * 272 + bColK + kk * 32);
                bfr[2*p][0] = m4[0]; bfr[2*p][1] = m4[1];
                bfr[2*p+1][0] = m4[2]; bfr[2*p+1][1] = m4[3];
            }
            #pragma unroll
            for (int nt = 0; nt < 8; nt++)
                mma16(sacc[nt], qf[kk], bfr[nt]);
        }

        float mb0 = -1e30f, mb1 = -1e30f;
        #pragma unroll
        for (int nt = 0; nt < 8; nt++) {
            const int kc = c * 64 + nt * 8 + (lane & 3) * 2;
            float2 bb0 = *(const float2*)&bias[(size_t)qr0 * S_ + kc];
            float2 bb1 = *(const float2*)&bias[(size_t)(qr0 + 8) * S_ + kc];
            sacc[nt][0] = sacc[nt][0] * isd + bb0.x;
            sacc[nt][1] = sacc[nt][1] * isd + bb0.y;
            sacc[nt][2] = sacc[nt][2] * isd + bb1.x;
            sacc[nt][3] = sacc[nt][3] * isd + bb1.y;
            mb0 = fmaxf(mb0, fmaxf(sacc[nt][0], sacc[nt][1]));
            mb1 = fmaxf(mb1, fmaxf(sacc[nt][2], sacc[nt][3]));
        }
        #pragma unroll
        for (int d = 1; d <= 2; d <<= 1) {
            mb0 = fmaxf(mb0, __shfl_xor_sync(0xffffffffu, mb0, d));
            mb1 = fmaxf(mb1, __shfl_xor_sync(0xffffffffu, mb1, d));
        }
        const float mn0 = fmaxf(mrow[0], mb0), mn1 = fmaxf(mrow[1], mb1);
        const float f0 = __expf(mrow[0] - mn0), f1 = __expf(mrow[1] - mn1);
        mrow[0] = mn0; mrow[1] = mn1;
        lrow[0] *= f0; lrow[1] *= f1;
        #pragma unroll
        for (int nt = 0; nt < 16; nt++) {
            acc_o[nt][0] *= f0; acc_o[nt][1] *= f0;
            acc_o[nt][2] *= f1; acc_o[nt][3] *= f1;
        }

        uint32_t ph[8][2];
        float ls0 = 0.f, ls1 = 0.f;
        #pragma unroll
        for (int nt = 0; nt < 8; nt++) {
            float p0 = __expf(sacc[nt][0] - mn0);
            float p1 = __expf(sacc[nt][1] - mn0);
            float p2 = __expf(sacc[nt][2] - mn1);
            float p3 = __expf(sacc[nt][3] - mn1);
            ls0 += p0 + p1; ls1 += p2 + p3;
            ph[nt][0] = h2u(__floats2half2_rn(p0, p1));
            ph[nt][1] = h2u(__floats2half2_rn(p2, p3));
        }
        #pragma unroll
        for (int d = 1; d <= 2; d <<= 1) {
            ls0 += __shfl_xor_sync(0xffffffffu, ls0, d);
            ls1 += __shfl_xor_sync(0xffffffffu, ls1, d);
        }
        lrow[0] += ls0; lrow[1] += ls1;

        #pragma unroll
        for (int kk = 0; kk < 4; kk++) {
            uint32_t af[4];
            af[0] = ph[2*kk][0]; af[1] = ph[2*kk][1];
            af[2] = ph[2*kk+1][0]; af[3] = ph[2*kk+1][1];
            #pragma unroll
            for (int p = 0; p < 8; p++) {
                uint32_t m4[4];
                ldsm_x4(m4, vb + (bRow + p * 16) * 144 + bColK + kk * 32);
                uint32_t bf0[2] = {m4[0], m4[1]};
                uint32_t bf1[2] = {m4[2], m4[3]};
                mma16(acc_o[2*p], af, bf0);
                mma16(acc_o[2*p+1], af, bf1);
            }
        }
        __syncthreads();
    }
    #undef ISSUE_KV

    const float inv0 = 1.f / lrow[0], inv1 = 1.f / lrow[1];
    h16* crow0 = ctx + (size_t)qr0 * D_ + h * DH_;
    h16* crow1 = crow0 + (size_t)8 * D_;
    #pragma unroll
    for (int nt = 0; nt < 16; nt++) {
        const int cc = nt * 8 + (lane & 3) * 2;
        *(__half2*)&crow0[cc] = __floats2half2_rn(acc_o[nt][0] * inv0, acc_o[nt][1] * inv0);
        *(__half2*)&crow1[cc] = __floats2half2_rn(acc_o[nt][2] * inv1, acc_o[nt][3] * inv1);
    }
}

// ---------- transpose-convert: [R][C] fp32 -> [C][R] fp16, 64x64 --------------
__global__ __launch_bounds__(256) void tcvt64(
    const float* __restrict__ in, h16* __restrict__ out,
    int ldin, long long zin, int ldout, long long zout)
{
    __shared__ float sm[64][66];
    in  += (long long)blockIdx.z * zin;
    out += (long long)blockIdx.z * zout;
    int c0 = blockIdx.x * 64, r0 = blockIdx.y * 64;
    int tid = threadIdx.x;
    int lr = tid >> 4, lc4 = (tid & 15) * 4;
    #pragma unroll
    for (int i = 0; i < 4; i++) {
        float4 v = *(const float4*)&in[(long long)(r0 + lr + i*16) * ldin + c0 + lc4];
        sm[lr + i*16][lc4 + 0] = v.x; sm[lr + i*16][lc4 + 1] = v.y;
        sm[lr + i*16][lc4 + 2] = v.z; sm[lr + i*16][lc4 + 3] = v.w;
    }
    __syncthreads();
    int oc = tid >> 4, or4 = (tid & 15) * 4;
    #pragma unroll
    for (int i = 0; i < 4; i++) {
        int c = oc + i * 16;
        uint2 w;
        h16* wb = (h16*)&w;
        wb[0] = __float2half_rn(sm[or4 + 0][c]);
        wb[1] = __float2half_rn(sm[or4 + 1][c]);
        wb[2] = __float2half_rn(sm[or4 + 2][c]);
        wb[3] = __float2half_rn(sm[or4 + 3][c]);
        *(uint2*)&out[(long long)(c0 + c) * ldout + r0 + or4] = w;
    }
}

// ---------- batched 4-weight transpose-convert (D x D each, z = weight) ------
__global__ __launch_bounds__(256) void tcvt64b(P4 io)
{
    __shared__ float sm[64][66];
    const float* in = io.in[blockIdx.z];
    h16* out = io.out[blockIdx.z];
    int c0 = blockIdx.x * 64, r0 = blockIdx.y * 64;
    int tid = threadIdx.x;
    int lr = tid >> 4, lc4 = (tid & 15) * 4;
    #pragma unroll
    for (int i = 0; i < 4; i++) {
        float4 v = *(const float4*)&in[(long long)(r0 + lr + i*16) * D_ + c0 + lc4];
        sm[lr + i*16][lc4 + 0] = v.x; sm[lr + i*16][lc4 + 1] = v.y;
        sm[lr + i*16][lc4 + 2] = v.z; sm[lr + i*16][lc4 + 3] = v.w;
    }
    __syncthreads();
    int oc = tid >> 4, or4 = (tid & 15) * 4;
    #pragma unroll
    for (int i = 0; i < 4; i++) {
        int c = oc + i * 16;
        uint2 w;
        h16* wb = (h16*)&w;
        wb[0] = __float2half_rn(sm[or4 + 0][c]);
        wb[1] = __float2half_rn(sm[or4 + 1][c]);
        wb[2] = __float2half_rn(sm[or4 + 2][c]);
        wb[3] = __float2half_rn(sm[or4 + 3][c]);
        *(uint2*)&out[(long long)(c0 + c) * D_ + r0 + or4] = w;
    }
}

// ---------- h16 -> h16 transpose, 64x64 ---------------------------------------
__global__ __launch_bounds__(256) void tcvt16(
    const h16* __restrict__ in, h16* __restrict__ out,
    int ldin, long long zin, int ldout, long long zout)
{
    __shared__ h16 sm[64][68];
    in  += (long long)blockIdx.z * zin;
    out += (long long)blockIdx.z * zout;
    int c0 = blockIdx.x * 64, r0 = blockIdx.y * 64;
    int tid = threadIdx.x;
    int lr = tid >> 4, lc4 = (tid & 15) * 4;
    #pragma unroll
    for (int i = 0; i < 4; i++) {
        uint2 v = *(const uint2*)&in[(long long)(r0 + lr + i*16) * ldin + c0 + lc4];
        *(uint2*)&sm[lr + i*16][lc4] = v;
    }
    __syncthreads();
    int oc = tid >> 4, or4 = (tid & 15) * 4;
    #pragma unroll
    for (int i = 0; i < 4; i++) {
        int c = oc + i * 16;
        uint2 w;
        h16* wb = (h16*)&w;
        wb[0] = sm[or4 + 0][c]; wb[1] = sm[or4 + 1][c];
        wb[2] = sm[or4 + 2][c]; wb[3] = sm[or4 + 3][c];
        *(uint2*)&out[(long long)(c0 + c) * ldout + r0 + or4] = w;
    }
}

// ---------------- elementwise / reduction kernels ---------------------------
__global__ void reset_k() { int i = threadIdx.x; if (i < E_) g_cnt[i] = 0; }

__global__ void rmsnorm_k(const float* __restrict__ in, const float* __restrict__ w,
                          h16* __restrict__ outB, float* __restrict__ outRaw)
{
    int s = blockIdx.x;
    const float* x = in + (size_t)s * D_;
    float ss = 0.f;
    for (int d = threadIdx.x; d < D_; d += 256) { float v = x[d]; ss += v*v; }
    __shared__ float red[256];
    red[threadIdx.x] = ss; __syncthreads();
    for (int st = 128; st > 0; st >>= 1) {
        if (threadIdx.x < st) red[threadIdx.x] += red[threadIdx.x+st];
        __syncthreads();
    }
    float r = rsqrtf(red[0]/(float)D_ + EPS_);
    for (int d = threadIdx.x; d < D_; d += 256) {
        float v = x[d]*r*(1.f + w[d]);
        outB[(size_t)s*D_ + d] = __float2half_rn(v);
        if (outRaw) outRaw[(size_t)s*D_ + d] = v;
    }
}

__global__ void rope16_k(const h16* __restrict__ q, const h16* __restrict__ k,
                         h16* __restrict__ qo, h16* __restrict__ ko,
                         const float* __restrict__ cosp, const float* __restrict__ sinp)
{
    int idx = blockIdx.x*blockDim.x + threadIdx.x;
    if (idx >= S_*H_*64) return;
    int d = idx & 63;
    int h = (idx >> 6) & 15;
    int s = idx >> 10;
    float c1 = cosp[s*DH_ + d],      s1 = sinp[s*DH_ + d];
    float c2 = cosp[s*DH_ + d + 64], s2 = sinp[s*DH_ + d + 64];
    size_t base = (size_t)s*D_ + h*DH_ + d;
    float q1 = __half2float(q[base]), q2 = __half2float(q[base+64]);
    qo[base]    = __float2half_rn(q1*c1 - q2*s1);
    qo[base+64] = __float2half_rn(q2*c2 + q1*s2);
    float k1 = __half2float(k[base]), k2 = __half2float(k[base+64]);
    ko[base]    = __float2half_rn(k1*c1 - k2*s1);
    ko[base+64] = __float2half_rn(k2*c2 + k1*s2);
}

__global__ void sigmul16_k(const h16* __restrict__ ctx, const h16* __restrict__ gl,
                           h16* __restrict__ outp)
{
    int i = blockIdx.x*blockDim.x + threadIdx.x;
    if (i >= S_*D_) return;
    float g = __half2float(gl[i]);
    outp[i] = __float2half_rn(__half2float(ctx[i]) / (1.f + expf(-g)));
}

__global__ void silumul16_k(const h16* __restrict__ a, const h16* __restrict__ b,
                            h16* __restrict__ outp, int n)
{
    int i = blockIdx.x*blockDim.x + threadIdx.x;
    if (i >= n) return;
    float g = __half2float(a[i]);
    outp[i] = __float2half_rn(g / (1.f + expf(-g)) * __half2float(b[i]));
}

// router + gsig fused
__global__ void router_k(const float* __restrict__ Y, const float* __restrict__ Rw,
                         const float* __restrict__ gw)
{
    int t = blockIdx.x;
    int tid = threadIdx.x;
    float part[E_] = {};
    float gpart = 0.f;
    for (int d = tid; d < D_; d += 256) {
        float v = Y[(size_t)t*D_ + d];
        #pragma unroll
        for (int e = 0; e < E_; e++) part[e] += v * Rw[d*E_ + e];
        gpart += v * gw[d];
    }
    __shared__ float red[256];
    __shared__ float logits[E_];
    for (int e = 0; e < E_; e++) {
        red[tid] = part[e]; __syncthreads();
        for (int st = 128; st > 0; st >>= 1) {
            if (tid < st) red[tid] += red[tid+st];
            __syncthreads();
        }
        if (tid == 0) logits[e] = red[0];
        __syncthreads();
    }
    red[tid] = gpart; __syncthreads();
    for (int st = 128; st > 0; st >>= 1) {
        if (tid < st) red[tid] += red[tid+st];
        __syncthreads();
    }
    if (tid == 0) {
        g_gsig[t] = 1.f / (1.f + expf(-red[0]));
        float m = -1e30f;
        for (int e = 0; e < E_; e++) m = fmaxf(m, logits[e]);
        float p[E_], s = 0.f;
        for (int e = 0; e < E_; e++) { p[e] = expf(logits[e]-m); s += p[e]; }
        for (int e = 0; e < E_; e++) p[e] /= s;
        int i0 = 0;
        for (int e = 1; e < E_; e++) if (p[e] > p[i0]) i0 = e;
        int i1 = (i0 == 0) ? 1 : 0;
        for (int e = 0; e < E_; e++) if (e != i0 && p[e] > p[i1]) i1 = e;
        float sum = p[i0] + p[i1];
        g_eidx[t*2]   = i0; g_eidx[t*2+1] = i1;
        g_ew[t*2]     = p[i0]/sum;
        g_ew[t*2+1]   = p[i1]/sum;
        atomicAdd(&g_cnt[i0], 1);
        atomicAdd(&g_cnt[i1], 1);
    }
}

__global__ void offsets_k()
{
    if (threadIdx.x == 0 && blockIdx.x == 0) {
        int acc = 0;
        for (int e = 0; e < E_; e++) { g_off[e] = acc; g_fill[e] = acc; acc += g_cnt[e]; }
        g_off[E_] = acc;
    }
}

__global__ void scatter_k()
{
    int t = blockIdx.x*blockDim.x + threadIdx.x;
    if (t >= S_) return;
    #pragma unroll
    for (int k = 0; k < 2; k++) {
        int e = g_eidx[t*2+k];
        int pos = atomicAdd(&g_fill[e], 1);
        g_perm[pos] = t;
        g_slot[t*2+k] = pos;
    }
}

__global__ void final_k(float* __restrict__ out)
{
    int i = blockIdx.x*blockDim.x + threadIdx.x;
    if (i >= S_*D_) return;
    int t = i >> 11;
    int d = i & 2047;
    float m0 = g_ew[2*t]   * g_eo[(size_t)g_slot[2*t]  *D_ + d];
    float m1 = g_ew[2*t+1] * g_eo[(size_t)g_slot[2*t+1]*D_ + d];
    out[i] = g_hbuf[i] + m0 + m1 + g_shout[i]*g_gsig[t];
}

// ---------------- host launcher ---------------------------------------------
extern "C" void kernel_launch(void* const* d_in, const int* in_sizes, int n_in,
                              void* d_out, int out_size)
{
    const float* hidden = (const float*)d_in[0];
    const float* bias   = (const float*)d_in[1];
    const float* cosp   = (const float*)d_in[2];
    const float* sinp   = (const float*)d_in[3];
    const float* ln1w   = (const float*)d_in[4];
    const float* ln2w   = (const float*)d_in[5];
    const float* wq     = (const float*)d_in[6];
    const float* wk     = (const float*)d_in[7];
    const float* wv     = (const float*)d_in[8];
    const float* wg     = (const float*)d_in[9];
    const float* wo     = (const float*)d_in[10];
    const float* rw     = (const float*)d_in[11];
    const float* eg     = (const float*)d_in[12];
    const float* eu     = (const float*)d_in[13];
    const float* ed     = (const float*)d_in[14];
    const float* shg    = (const float*)d_in[15];
    const float* shu    = (const float*)d_in[16];
    const float* shd    = (const float*)d_in[17];
    const float* shgw   = (const float*)d_in[18];
    float* out = (float*)d_out;

    float *pq, *pk, *pv, *pgl, *pctx, *ph, *psgf, *pmactf, *pshout, *peo;
    cudaGetSymbolAddress((void**)&pq,    g_q);
    cudaGetSymbolAddress((void**)&pk,    g_k);
    cudaGetSymbolAddress((void**)&pv,    g_v);
    cudaGetSymbolAddress((void**)&pgl,   g_gl);
    cudaGetSymbolAddress((void**)&pctx,  g_ctx);
    cudaGetSymbolAddress((void**)&ph,    g_hbuf);
    cudaGetSymbolAddress((void**)&psgf,  g_sgf);
    cudaGetSymbolAddress((void**)&pmactf,g_mactf);
    cudaGetSymbolAddress((void**)&pshout,g_shout);
    cudaGetSymbolAddress((void**)&peo,   g_eo);

    h16 *bx, *bq, *bk, *bvT, *bup, *bup2, *bctx, *by, *bsg, *bmact;
    h16 *Bwq, *Bwk, *Bwv, *Bwg, *Bwo, *Bshg, *Bshu, *Bshd, *Beg, *Beu, *Bed;
    cudaGetSymbolAddress((void**)&bx,   b_x);
    cudaGetSymbolAddress((void**)&bq,   b_q);
    cudaGetSymbolAddress((void**)&bk,   b_k);
    cudaGetSymbolAddress((void**)&bvT,  b_vT);
    cudaGetSymbolAddress((void**)&bup,  b_up);
    cudaGetSymbolAddress((void**)&bup2, b_up2);
    cudaGetSymbolAddress((void**)&bctx, b_ctx);
    cudaGetSymbolAddress((void**)&by,   b_y);
    cudaGetSymbolAddress((void**)&bsg,  b_sg);
    cudaGetSymbolAddress((void**)&bmact,b_mact);
    cudaGetSymbolAddress((void**)&Bwq,  b_wq);
    cudaGetSymbolAddress((void**)&Bwk,  b_wk);
    cudaGetSymbolAddress((void**)&Bwv,  b_wv);
    cudaGetSymbolAddress((void**)&Bwg,  b_wg);
    cudaGetSymbolAddress((void**)&Bwo,  b_wo);
    cudaGetSymbolAddress((void**)&Bshg, b_shg);
    cudaGetSymbolAddress((void**)&Bshu, b_shu);
    cudaGetSymbolAddress((void**)&Bshd, b_shd);
    cudaGetSymbolAddress((void**)&Beg,  b_eg);
    cudaGetSymbolAddress((void**)&Beu,  b_eu);
    cudaGetSymbolAddress((void**)&Bed,  b_ed);

    h16* pq16   = (h16*)pq;
    h16* pk16   = (h16*)pk;
    h16* pv16   = (h16*)pv;
    h16* pgl16  = (h16*)pgl;
    h16* pctx16 = (h16*)pctx;
    h16* psg16  = (h16*)psgf;
    h16* pmact16= (h16*)pmactf;
    float* pyraw = pctx;

    const int SMEM = 110592;
    cudaFuncSetAttribute(bgemm<0,0>, cudaFuncAttributeMaxDynamicSharedMemorySize, SMEM);
    cudaFuncSetAttribute(bgemm<0,1>, cudaFuncAttributeMaxDynamicSharedMemorySize, SMEM);
    cudaFuncSetAttribute(bgemm<1,1>, cudaFuncAttributeMaxDynamicSharedMemorySize, SMEM);
    cudaFuncSetAttribute(bgemm<2,0>, cudaFuncAttributeMaxDynamicSharedMemorySize, SMEM);
    const int SMEM_F = 17408 + 2*17408 + 2*18432;   // 89088
    cudaFuncSetAttribute(flash_k, cudaFuncAttributeMaxDynamicSharedMemorySize, SMEM_F);

    const float isd = 0.08838834764831845f;

    static cudaStream_t s2 = nullptr;
    static cudaEvent_t ev0 = nullptr, evX = nullptr, evO = nullptr, evM = nullptr,
                       evY = nullptr, evSH = nullptr;
    if (!s2) {
        cudaStreamCreateWithFlags(&s2, cudaStreamNonBlocking);
        cudaEventCreateWithFlags(&ev0, cudaEventDisableTiming);
        cudaEventCreateWithFlags(&evX, cudaEventDisableTiming);
        cudaEventCreateWithFlags(&evO, cudaEventDisableTiming);
        cudaEventCreateWithFlags(&evM, cudaEventDisableTiming);
        cudaEventCreateWithFlags(&evY, cudaEventDisableTiming);
        cudaEventCreateWithFlags(&evSH, cudaEventDisableTiming);
    }

    // ---- fork immediately: rmsnorm1 + remaining conversions on s2;
    //      batched QKVG conversion on main (both latency-bound, overlap well)
    cudaEventRecord(ev0, 0);
    cudaStreamWaitEvent(s2, ev0, 0);
    rmsnorm_k<<<S_, 256, 0, s2>>>(hidden, ln1w, bx, nullptr);
    cudaEventRecord(evX, s2);
    tcvt64<<<dim3(32,32), 256, 0, s2>>>(wo, Bwo, D_, 0, D_, 0);
    cudaEventRecord(evO, s2);
    tcvt64<<<dim3(64,32), 256, 0, s2>>>(shg, Bshg, SFF_, 0, D_, 0);
    tcvt64<<<dim3(64,32), 256, 0, s2>>>(shu, Bshu, SFF_, 0, D_, 0);
    tcvt64<<<dim3(32,64), 256, 0, s2>>>(shd, Bshd, D_, 0, SFF_, 0);
    tcvt64<<<dim3(12,32,E_), 256, 0, s2>>>(eg, Beg, FF_, (long long)D_*FF_, D_, (long long)FF_*D_);
    tcvt64<<<dim3(12,32,E_), 256, 0, s2>>>(eu, Beu, FF_, (long long)D_*FF_, D_, (long long)FF_*D_);
    tcvt64<<<dim3(32,12,E_), 256, 0, s2>>>(ed, Bed, D_, (long long)FF_*D_, FF_, (long long)D_*FF_);
    cudaEventRecord(evM, s2);

    reset_k<<<1, 32>>>();
    {
        P4 io = {{wq, wk, wv, wg}, {Bwq, Bwk, Bwv, Bwg}};
        tcvt64b<<<dim3(32,32,4), 256>>>(io);
    }
    cudaStreamWaitEvent(0, evX, 0);

    // ---- attention (main) ----
    {
        BC4 bc = {{Bwq, Bwk, Bwv, Bwg}, {(float*)pq16, (float*)pk16, (float*)pv16, (float*)pgl16}};
        bgemm<0,1><<<dim3(64,16), 256, SMEM>>>(bx, D_, 0, bc, D_, 0, D_, 0,
                                               nullptr, 0, 0, S_, 8192, D_, 1.f, 2048);
    }
    rope16_k<<<(S_*H_*64 + 255)/256, 256>>>(pq16, pk16, bq, bk, cosp, sinp);
    tcvt16<<<dim3(2,32,H_), 256>>>(pv16, bvT, D_, 128LL, S_, (long long)DH_*S_);

    flash_k<<<dim3(S_/64, H_), 128, SMEM_F>>>(bq, bk, bvT, bias, pctx16, isd);

    sigmul16_k<<<(S_*D_ + 255)/256, 256>>>(pctx16, pgl16, bctx);
    cudaStreamWaitEvent(0, evO, 0);
    {
        BC4 bc = {{Bwo, 0, 0, 0}, {ph, 0, 0, 0}};
        bgemm<0,0><<<dim3(16,16), 256, SMEM>>>(bctx, D_, 0, bc, D_, 0, D_, 0,
                                               hidden, D_, 0, S_, D_, D_, 1.f, 2048);
    }

    // ---- y (main); fork shared-expert chain to s2 ----
    rmsnorm_k<<<S_, 256>>>(ph, ln2w, by, pyraw);
    cudaEventRecord(evY, 0);
    cudaStreamWaitEvent(s2, evY, 0);
    {
        BC4 bc = {{Bshg, Bshu, 0, 0}, {(float*)psg16, (float*)bup, 0, 0}};
        bgemm<0,1><<<dim3(64,16), 256, SMEM, s2>>>(by, D_, 0, bc, D_, 0, SFF_, 0,
                                                   nullptr, 0, 0, S_, 8192, D_, 1.f, 4096);
    }
    silumul16_k<<<(S_*SFF_ + 255)/256, 256, 0, s2>>>(psg16, bup, bsg, S_*SFF_);
    {
        BC4 bc = {{Bshd, 0, 0, 0}, {pshout, 0, 0, 0}};
        bgemm<0,0><<<dim3(16,16), 256, SMEM, s2>>>(bsg, SFF_, 0, bc, SFF_, 0, D_, 0,
                                                   nullptr, 0, 0, S_, D_, SFF_, 1.f, 2048);
    }
    cudaEventRecord(evSH, s2);

    // ---- routing (main, overlaps shared expert) ----
    router_k<<<S_, 256>>>(pyraw, rw, shgw);
    offsets_k<<<1, 1>>>();
    scatter_k<<<(S_ + 255)/256, 256>>>();

    // ---- MoE experts (main) ----
    cudaStreamWaitEvent(0, evM, 0);
    {
        BC4 bc = {{Beg, Beu, 0, 0}, {(float*)pmact16, (float*)bup2, 0, 0}};
        bgemm<1,1><<<dim3(12,16,E_), 256, SMEM>>>(by, D_, 0, bc, D_, (long long)FF_*D_,
                                                  FF_, 0, nullptr, 0, 0,
                                                  0, 1536, D_, 1.f, 768);
    }
    silumul16_k<<<(S_*2*FF_ + 255)/256, 256>>>(pmact16, bup2, bmact, S_*2*FF_);
    {
        BC4 bc = {{Bed, 0, 0, 0}, {peo, 0, 0, 0}};
        bgemm<2,0><<<dim3(16,16,E_), 256, SMEM>>>(bmact, FF_, 0, bc, FF_, (long long)D_*FF_,
                                                  D_, 0, nullptr, 0, 0,
                                                  0, D_, FF_, 1.f, 2048);
    }

    cudaStreamWaitEvent(0, evSH, 0);
    final_k<<<(S_*D_ + 255)/256, 256>>>(out);
}